// round 10
// baseline (speedup 1.0000x reference)
#include <cuda_runtime.h>

#define T_  128
#define B_  64
#define D_  1024
#define TB_ (T_*B_)
#define D3_ (3*D_)
#define D9_ (9*D_)

typedef unsigned long long ull;

// ---------------- static scratch (no allocation anywhere) ----------------
__device__ float g_FA[TB_*D_];
__device__ float g_FB[TB_*D_];
__device__ float g_FC[TB_*D_];
__device__ float g_Sinv[TB_*D_];
__device__ float g_S[TB_*D_];
__device__ float g_GI[TB_*D3_];
__device__ float g_Wbq[B_*D_];
__device__ float g_Wbm[B_*D_];
__device__ float g_rc[B_*D_];
__device__ float g_h0[B_*D_];
__device__ float g_h1[B_*D_];
__device__ float g_m[B_*D_];
__device__ float g_m2[B_*D_];
__device__ float g_gi[B_*D3_];
__device__ float g_gh[B_*D3_];

// ---------------- helpers ----------------
__device__ __forceinline__ void ffma2(ull& c, ull a, ull b) {
    asm("fma.rn.f32x2 %0, %1, %2, %0;" : "+l"(c) : "l"(a), "l"(b));
}
__device__ __forceinline__ ull pk(float lo, float hi) {
    ull r; asm("mov.b64 %0, {%1, %2};" : "=l"(r) : "f"(lo), "f"(hi)); return r;
}
__device__ __forceinline__ float2 upk(ull a) {
    float2 v; asm("mov.b64 {%0, %1}, %2;" : "=f"(v.x), "=f"(v.y) : "l"(a)); return v;
}
__device__ __forceinline__ float sum2(ull a) { float2 v = upk(a); return v.x + v.y; }
__device__ __forceinline__ float sigf(float x)     { return 1.f / (1.f + __expf(-x)); }
__device__ __forceinline__ float tanhfast(float x) { return 2.f / (1.f + __expf(-2.f*x)) - 1.f; }

// ---------------- generic SGEMM: C[M,N] (+)= A[M,K] @ W[N,K]^T ----------------
// Row-major everywhere. N must be a multiple of 64, K a multiple of 16.
#define BM 128
#define BN 64
#define BK 16

__global__ __launch_bounds__(256) void gemm_kernel(
    const float* __restrict__ A, int ldA,
    const float* __restrict__ W, int ldW,
    float* __restrict__ C, int ldC,
    int M, int K, int accum)
{
    __shared__ float As[BK][BM+4];
    __shared__ float Ws[BK][BN+4];
    const int tid = threadIdx.x;
    const int bm = blockIdx.y * BM;
    const int bn = blockIdx.x * BN;
    const int tx = tid & 15, ty = tid >> 4;
    const int m0 = ty << 3, n0 = tx << 2;

    ull acc[4][4];
#pragma unroll
    for (int i = 0; i < 4; i++)
#pragma unroll
        for (int j = 0; j < 4; j++) acc[i][j] = 0ull;

    const int am0 = tid >> 2, ak0 = (tid & 3) << 2;
    const int am1 = am0 + 64;
    const int wn  = tid >> 2, wk  = ak0;
    const bool av0 = (bm + am0) < M;
    const bool av1 = (bm + am1) < M;
    const float* Ap0 = A + (size_t)(bm + am0) * ldA + ak0;
    const float* Ap1 = A + (size_t)(bm + am1) * ldA + ak0;
    const float* Wp  = W + (size_t)(bn + wn)  * ldW + wk;
    const float4 z4 = make_float4(0.f, 0.f, 0.f, 0.f);

    float4 ra0 = av0 ? *(const float4*)Ap0 : z4;
    float4 ra1 = av1 ? *(const float4*)Ap1 : z4;
    float4 rw  = *(const float4*)Wp;

    for (int k0 = 0; k0 < K; k0 += BK) {
        As[ak0+0][am0] = ra0.x; As[ak0+1][am0] = ra0.y; As[ak0+2][am0] = ra0.z; As[ak0+3][am0] = ra0.w;
        As[ak0+0][am1] = ra1.x; As[ak0+1][am1] = ra1.y; As[ak0+2][am1] = ra1.z; As[ak0+3][am1] = ra1.w;
        Ws[wk+0][wn] = rw.x; Ws[wk+1][wn] = rw.y; Ws[wk+2][wn] = rw.z; Ws[wk+3][wn] = rw.w;
        __syncthreads();
        if (k0 + BK < K) {
            ra0 = av0 ? *(const float4*)(Ap0 + k0 + BK) : z4;
            ra1 = av1 ? *(const float4*)(Ap1 + k0 + BK) : z4;
            rw  = *(const float4*)(Wp + k0 + BK);
        }
#pragma unroll
        for (int kk = 0; kk < BK; kk++) {
            const float* ar = &As[kk][m0];
            ull a0 = *(const ull*)(ar + 0);
            ull a1 = *(const ull*)(ar + 2);
            ull a2 = *(const ull*)(ar + 4);
            ull a3 = *(const ull*)(ar + 6);
            float4 wq = *(const float4*)&Ws[kk][n0];
            ull w0 = pk(wq.x, wq.x), w1 = pk(wq.y, wq.y);
            ull w2 = pk(wq.z, wq.z), w3 = pk(wq.w, wq.w);
            ffma2(acc[0][0], a0, w0); ffma2(acc[0][1], a0, w1); ffma2(acc[0][2], a0, w2); ffma2(acc[0][3], a0, w3);
            ffma2(acc[1][0], a1, w0); ffma2(acc[1][1], a1, w1); ffma2(acc[1][2], a1, w2); ffma2(acc[1][3], a1, w3);
            ffma2(acc[2][0], a2, w0); ffma2(acc[2][1], a2, w1); ffma2(acc[2][2], a2, w2); ffma2(acc[2][3], a2, w3);
            ffma2(acc[3][0], a3, w0); ffma2(acc[3][1], a3, w1); ffma2(acc[3][2], a3, w2); ffma2(acc[3][3], a3, w3);
        }
        __syncthreads();
    }

#pragma unroll
    for (int i = 0; i < 4; i++) {
        float2 v0 = upk(acc[i][0]), v1 = upk(acc[i][1]);
        float2 v2 = upk(acc[i][2]), v3 = upk(acc[i][3]);
        int gm = bm + m0 + 2 * i;
        float* p0 = C + (size_t)gm * ldC + bn + n0;
        if (gm < M) {
            float4 o = make_float4(v0.x, v1.x, v2.x, v3.x);
            if (accum) { float4 d = *(const float4*)p0; o.x += d.x; o.y += d.y; o.z += d.z; o.w += d.w; }
            *(float4*)p0 = o;
        }
        if (gm + 1 < M) {
            float* p1 = p0 + ldC;
            float4 o = make_float4(v0.y, v1.y, v2.y, v3.y);
            if (accum) { float4 d = *(const float4*)p1; o.x += d.x; o.y += d.y; o.z += d.z; o.w += d.w; }
            *(float4*)p1 = o;
        }
    }
}

// ---------------- fused GRU step: h_out = GRU+gate(h_in) for one t ----------------
// 128 blocks x 256 threads. Block handles d-columns [blk*8, blk*8+8), all 64 b.
// Warp w -> column d = blk*8+w; lane handles b = lane and b = lane+32.
__global__ __launch_bounds__(256) void step_kernel(
    const float* __restrict__ h_in, float* __restrict__ h_out,
    const float* __restrict__ gi,   // [64][3072] slice for this t (no bih)
    const float* __restrict__ gg,   // [64][1024] gate slice for this t
    const float* __restrict__ Whh,  // [3072][1024]
    const float* __restrict__ bih, const float* __restrict__ bhh)
{
    __shared__ float hs[128][65];    // h tile transposed [k][b]
    __shared__ float ws[24][132];    // 3 gates x 8 cols, [row][k]
    const int tid = threadIdx.x, lane = tid & 31, w = tid >> 5;
    const int d = blockIdx.x * 8 + w;

    ull ar0 = 0, az0 = 0, an0 = 0, ar1 = 0, az1 = 0, an1 = 0;

    for (int k0 = 0; k0 < 1024; k0 += 128) {
#pragma unroll
        for (int r = 0; r < 8; r++) {
            int id = tid + 256 * r;              // 2048 float4 of h tile
            int b = id >> 5, kq = (id & 31) << 2;
            float4 v = *(const float4*)(h_in + b * 1024 + k0 + kq);
            hs[kq+0][b] = v.x; hs[kq+1][b] = v.y; hs[kq+2][b] = v.z; hs[kq+3][b] = v.w;
        }
#pragma unroll
        for (int r = 0; r < 3; r++) {
            int id = tid + 256 * r;              // 768 float4 of w tile
            int row = id >> 5, kq = (id & 31) << 2;
            int gate = row >> 3, dc = blockIdx.x * 8 + (row & 7);
            float4 v = *(const float4*)(Whh + (size_t)(gate * 1024 + dc) * 1024 + k0 + kq);
            *(float4*)&ws[row][kq] = v;
        }
        __syncthreads();
        const float* wr = ws[w];
        const float* wz = ws[8 + w];
        const float* wn = ws[16 + w];
#pragma unroll 8
        for (int kk = 0; kk < 128; kk += 2) {
            ull h0 = pk(hs[kk][lane],      hs[kk+1][lane]);
            ull h1 = pk(hs[kk][lane+32],   hs[kk+1][lane+32]);
            ull vr = *(const ull*)&wr[kk];
            ull vz = *(const ull*)&wz[kk];
            ull vn = *(const ull*)&wn[kk];
            ffma2(ar0, h0, vr); ffma2(az0, h0, vz); ffma2(an0, h0, vn);
            ffma2(ar1, h1, vr); ffma2(az1, h1, vz); ffma2(an1, h1, vn);
        }
        __syncthreads();
    }

    const float bir = bih[d], biz = bih[1024 + d], bin = bih[2048 + d];
    const float bhr = bhh[d], bhz = bhh[1024 + d], bhn = bhh[2048 + d];
#pragma unroll
    for (int half = 0; half < 2; half++) {
        int b = lane + 32 * half;
        float dr = half ? sum2(ar1) : sum2(ar0);
        float dz = half ? sum2(az1) : sum2(az0);
        float dn = half ? sum2(an1) : sum2(an0);
        float gir = gi[b * 3072 + d]         + bir;
        float giz = gi[b * 3072 + 1024 + d]  + biz;
        float gin = gi[b * 3072 + 2048 + d]  + bin;
        float r = sigf(gir + dr + bhr);
        float z = sigf(giz + dz + bhz);
        float n = tanhfast(gin + r * (dn + bhn));
        float hp = h_in[b * 1024 + d];
        float hatt = (1.f - z) * n + z * hp;
        float G = gg[b * 1024 + d];
        h_out[b * 1024 + d] = G * hatt + (1.f - G) * hp;
    }
}

// ---------------- elementwise kernels ----------------
// feature builder: FA = c*x_row, FB = |c - x_row|, FC = c*y_row   (x,y are [64][1024])
__global__ void feat3_kernel(const float* __restrict__ c, const float* __restrict__ x,
                             const float* __restrict__ y, float* __restrict__ FA,
                             float* __restrict__ FB, float* __restrict__ FC)
{
    int i = blockIdx.x * 256 + threadIdx.x;        // float4 index over TB*D/4
    int bc = ((i >> 8) & 63) * 256 + (i & 255);
    float4 cv = ((const float4*)c)[i];
    float4 xv = ((const float4*)x)[bc];
    float4 yv = ((const float4*)y)[bc];
    ((float4*)FA)[i] = make_float4(cv.x*xv.x, cv.y*xv.y, cv.z*xv.z, cv.w*xv.w);
    ((float4*)FB)[i] = make_float4(fabsf(cv.x-xv.x), fabsf(cv.y-xv.y), fabsf(cv.z-xv.z), fabsf(cv.w-xv.w));
    ((float4*)FC)[i] = make_float4(cv.x*yv.x, cv.y*yv.y, cv.z*yv.z, cv.w*yv.w);
}

__global__ void addrow_kernel(const float* __restrict__ S0, const float* __restrict__ rc,
                              float* __restrict__ S)
{
    int i = blockIdx.x * 256 + threadIdx.x;
    int bc = ((i >> 8) & 63) * 256 + (i & 255);
    float4 a = ((const float4*)S0)[i];
    float4 r = ((const float4*)rc)[bc];
    ((float4*)S)[i] = make_float4(a.x+r.x, a.y+r.y, a.z+r.z, a.w+r.w);
}

__global__ void tanh_kernel(float* __restrict__ S)
{
    int i = blockIdx.x * 256 + threadIdx.x;
    float4 v = ((float4*)S)[i];
    ((float4*)S)[i] = make_float4(tanhfast(v.x), tanhfast(v.y), tanhfast(v.z), tanhfast(v.w));
}

__global__ void sigbias_kernel(float* __restrict__ G, const float* __restrict__ bias)
{
    int i = blockIdx.x * 256 + threadIdx.x;
    float4 b = ((const float4*)bias)[i & 255];
    float4 v = ((float4*)G)[i];
    ((float4*)G)[i] = make_float4(sigf(v.x+b.x), sigf(v.y+b.y), sigf(v.z+b.z), sigf(v.w+b.w));
}

__global__ void rowbias_kernel(float* __restrict__ rc, const float* __restrict__ bias)
{
    int i = blockIdx.x * 256 + threadIdx.x;        // B*D/4 = 16384
    float4 b = ((const float4*)bias)[i & 255];
    float4 v = ((float4*)rc)[i];
    ((float4*)rc)[i] = make_float4(v.x+b.x, v.y+b.y, v.z+b.z, v.w+b.w);
}

__global__ void zero_kernel(float* __restrict__ p)
{
    int i = blockIdx.x * 256 + threadIdx.x;        // B*D/4
    ((float4*)p)[i] = make_float4(0.f, 0.f, 0.f, 0.f);
}

// final memory-GRU: m_new = GRUCell(e, m) elementwise (gi = e@Wih^T, gh = m@Whh^T, no biases folded yet)
__global__ void gruew_kernel(const float* __restrict__ gi, const float* __restrict__ gh,
                             const float* __restrict__ h,  const float* __restrict__ bih,
                             const float* __restrict__ bhh, float* __restrict__ out)
{
    int i = blockIdx.x * 256 + threadIdx.x;        // 65536
    int b = i >> 10, d = i & 1023;
    float gir = gi[b*3072 + d]        + bih[d];
    float giz = gi[b*3072 + 1024 + d] + bih[1024 + d];
    float gin = gi[b*3072 + 2048 + d] + bih[2048 + d];
    float ghr = gh[b*3072 + d]        + bhh[d];
    float ghz = gh[b*3072 + 1024 + d] + bhh[1024 + d];
    float ghn = gh[b*3072 + 2048 + d] + bhh[2048 + d];
    float r = sigf(gir + ghr);
    float z = sigf(giz + ghz);
    float n = tanhfast(gin + r * ghn);
    out[i] = (1.f - z) * n + z * h[i];
}

// ---------------- host orchestration ----------------
static void gemm(const float* A, int ldA, const float* W, int ldW,
                 float* C, int ldC, int M, int N, int K, int accum)
{
    dim3 g(N / BN, (M + BM - 1) / BM);
    gemm_kernel<<<g, 256>>>(A, ldA, W, ldW, C, ldC, M, K, accum);
}

extern "C" void kernel_launch(void* const* d_in, const int* in_sizes, int n_in,
                              void* d_out, int out_size)
{
    const float* c    = (const float*)d_in[0];
    const float* q    = (const float*)d_in[1];
    const float* Wb   = (const float*)d_in[2];
    const float* W1   = (const float*)d_in[3];
    const float* W1b  = (const float*)d_in[4];
    const float* W2   = (const float*)d_in[5];
    const float* W2b  = (const float*)d_in[6];
    const float* mWih = (const float*)d_in[7];
    const float* mWhh = (const float*)d_in[8];
    const float* mbih = (const float*)d_in[9];
    const float* mbhh = (const float*)d_in[10];
    const float* aWih = (const float*)d_in[11];
    const float* aWhh = (const float*)d_in[12];
    const float* abih = (const float*)d_in[13];
    const float* abhh = (const float*)d_in[14];

    float *pFA, *pFB, *pFC, *pSinv, *pS, *pGI, *pWbq, *pWbm, *prc;
    float *ph0, *ph1, *pm, *pm2, *pgi, *pgh;
    cudaGetSymbolAddress((void**)&pFA,   g_FA);
    cudaGetSymbolAddress((void**)&pFB,   g_FB);
    cudaGetSymbolAddress((void**)&pFC,   g_FC);
    cudaGetSymbolAddress((void**)&pSinv, g_Sinv);
    cudaGetSymbolAddress((void**)&pS,    g_S);
    cudaGetSymbolAddress((void**)&pGI,   g_GI);
    cudaGetSymbolAddress((void**)&pWbq,  g_Wbq);
    cudaGetSymbolAddress((void**)&pWbm,  g_Wbm);
    cudaGetSymbolAddress((void**)&prc,   g_rc);
    cudaGetSymbolAddress((void**)&ph0,   g_h0);
    cudaGetSymbolAddress((void**)&ph1,   g_h1);
    cudaGetSymbolAddress((void**)&pm,    g_m);
    cudaGetSymbolAddress((void**)&pm2,   g_m2);
    cudaGetSymbolAddress((void**)&pgi,   g_gi);
    cudaGetSymbolAddress((void**)&pgh,   g_gh);

    const int GRID_TBD4 = (TB_ * D_ / 4) / 256;   // 8192
    const int GRID_BD4  = (B_ * D_ / 4) / 256;    // 64
    const int GRID_BD   = (B_ * D_) / 256;        // 256

    // m = q
    cudaMemcpyAsync(pm, q, (size_t)B_ * D_ * sizeof(float), cudaMemcpyDeviceToDevice);

    // episode-invariant precompute
    gemm(q, D_, Wb, D_, pWbq, D_, B_, D_, D_, 0);                 // Wbq = q @ Wb^T
    feat3_kernel<<<GRID_TBD4, 256>>>(c, q, pWbq, pFA, pFB, pFC);  // c*q, |c-q|, c*Wbq
    gemm(c,   D_, W1 + 0*D_, D9_, pSinv, D_, TB_, D_, D_, 0);     // c      @ V0^T
    gemm(pFA, D_, W1 + 3*D_, D9_, pSinv, D_, TB_, D_, D_, 1);     // c*q    @ V3^T
    gemm(pFB, D_, W1 + 5*D_, D9_, pSinv, D_, TB_, D_, D_, 1);     // |c-q|  @ V5^T
    gemm(pFC, D_, W1 + 7*D_, D9_, pSinv, D_, TB_, D_, D_, 1);     // c*Wbq  @ V7^T
    gemm(c, D_, aWih, D_, pGI, D3_, TB_, D3_, D_, 0);             // gi_att for all t

    float* mc = pm;
    float* mn = pm2;
    for (int ep = 0; ep < 2; ep++) {
        gemm(mc, D_, Wb, D_, pWbm, D_, B_, D_, D_, 0);            // Wbm = m @ Wb^T
        gemm(mc, D_, W1 + 1*D_, D9_, prc, D_, B_, D_, D_, 0);     // m @ V1^T
        gemm(q,  D_, W1 + 2*D_, D9_, prc, D_, B_, D_, D_, 1);     // + q @ V2^T
        rowbias_kernel<<<GRID_BD4, 256>>>(prc, W1b);              // + W1_b
        feat3_kernel<<<GRID_TBD4, 256>>>(c, mc, pWbm, pFA, pFB, pFC);
        addrow_kernel<<<GRID_TBD4, 256>>>(pSinv, prc, pS);        // S = Sinv + rowconst
        gemm(pFA, D_, W1 + 4*D_, D9_, pS, D_, TB_, D_, D_, 1);    // + c*m   @ V4^T
        gemm(pFB, D_, W1 + 6*D_, D9_, pS, D_, TB_, D_, D_, 1);    // + |c-m| @ V6^T
        gemm(pFC, D_, W1 + 8*D_, D9_, pS, D_, TB_, D_, D_, 1);    // + c*Wbm @ V8^T
        tanh_kernel<<<GRID_TBD4, 256>>>(pS);                      // g1 = tanh(S) in place
        gemm(pS, D_, W2, D_, pFA, D_, TB_, D_, D_, 0);            // Gpre = g1 @ W2^T (into FA)
        sigbias_kernel<<<GRID_TBD4, 256>>>(pFA, W2b);             // G = sigmoid(Gpre + b2)

        zero_kernel<<<GRID_BD4, 256>>>(ph0);                      // h = 0
        float* hin = ph0;
        float* hout = ph1;
        for (int t = 0; t < T_; t++) {
            step_kernel<<<128, 256>>>(hin, hout,
                                      pGI + (size_t)t * B_ * D3_,
                                      pFA + (size_t)t * B_ * D_,
                                      aWhh, abih, abhh);
            float* tmp = hin; hin = hout; hout = tmp;
        }
        // episode output e = hin (result of last step after swap)
        gemm(hin, D_, mWih, D_, pgi, D3_, B_, D3_, D_, 0);        // e @ mem_Wih^T
        gemm(mc,  D_, mWhh, D_, pgh, D3_, B_, D3_, D_, 0);        // m @ mem_Whh^T
        gruew_kernel<<<GRID_BD, 256>>>(pgi, pgh, mc, mbih, mbhh, mn);
        float* tmp = mc; mc = mn; mn = tmp;
    }

    cudaMemcpyAsync(d_out, mc, (size_t)B_ * D_ * sizeof(float), cudaMemcpyDeviceToDevice);
}

// round 11
// speedup vs baseline: 1.1763x; 1.1763x over previous
#include <cuda_runtime.h>
#include <stdint.h>

#define T_  128
#define B_  64
#define D_  1024
#define TB_ (T_*B_)
#define D3_ (3*D_)
#define D9_ (9*D_)

typedef unsigned long long ull;

// ---------------- static scratch (no allocation anywhere) ----------------
__device__ float g_FA[TB_*D_];
__device__ float g_FB[TB_*D_];
__device__ float g_FC[TB_*D_];
__device__ float g_Sinv[TB_*D_];
__device__ float g_S[TB_*D_];
__device__ float g_GI[TB_*D3_];
__device__ float g_Wbq[B_*D_];
__device__ float g_Wbm[B_*D_];
__device__ float g_rc[B_*D_];
__device__ float g_h0[B_*D_];
__device__ float g_h1[B_*D_];
__device__ float g_m[B_*D_];
__device__ float g_m2[B_*D_];
__device__ float g_gi[B_*D3_];
__device__ float g_gh[B_*D3_];

// ---------------- helpers ----------------
__device__ __forceinline__ void ffma2(ull& c, ull a, ull b) {
    asm("fma.rn.f32x2 %0, %1, %2, %0;" : "+l"(c) : "l"(a), "l"(b));
}
__device__ __forceinline__ ull pk(float lo, float hi) {
    ull r; asm("mov.b64 %0, {%1, %2};" : "=l"(r) : "f"(lo), "f"(hi)); return r;
}
__device__ __forceinline__ float2 upk(ull a) {
    float2 v; asm("mov.b64 {%0, %1}, %2;" : "=f"(v.x), "=f"(v.y) : "l"(a)); return v;
}
__device__ __forceinline__ float sum2(ull a) { float2 v = upk(a); return v.x + v.y; }
__device__ __forceinline__ float sigf(float x)     { return 1.f / (1.f + __expf(-x)); }
__device__ __forceinline__ float tanhfast(float x) { return 2.f / (1.f + __expf(-2.f*x)) - 1.f; }

__device__ __forceinline__ void cpasync16(uint32_t dst, const void* src) {
    asm volatile("cp.async.cg.shared.global [%0], [%1], 16;" :: "r"(dst), "l"(src));
}
__device__ __forceinline__ void cpcommit() { asm volatile("cp.async.commit_group;"); }
__device__ __forceinline__ void cpwait1()  { asm volatile("cp.async.wait_group 1;"); }
__device__ __forceinline__ void cpwait0()  { asm volatile("cp.async.wait_group 0;"); }

// ---------------- generic SGEMM: C[M,N] (+)= A[M,K] @ W[N,K]^T ----------------
#define BM 128
#define BN 64
#define BK 16

__global__ __launch_bounds__(256) void gemm_kernel(
    const float* __restrict__ A, int ldA,
    const float* __restrict__ W, int ldW,
    float* __restrict__ C, int ldC,
    int M, int K, int accum)
{
    __shared__ float As[BK][BM+4];
    __shared__ float Ws[BK][BN+4];
    const int tid = threadIdx.x;
    const int bm = blockIdx.y * BM;
    const int bn = blockIdx.x * BN;
    const int tx = tid & 15, ty = tid >> 4;
    const int m0 = ty << 3, n0 = tx << 2;

    ull acc[4][4];
#pragma unroll
    for (int i = 0; i < 4; i++)
#pragma unroll
        for (int j = 0; j < 4; j++) acc[i][j] = 0ull;

    const int am0 = tid >> 2, ak0 = (tid & 3) << 2;
    const int am1 = am0 + 64;
    const int wn  = tid >> 2, wk  = ak0;
    const bool av0 = (bm + am0) < M;
    const bool av1 = (bm + am1) < M;
    const float* Ap0 = A + (size_t)(bm + am0) * ldA + ak0;
    const float* Ap1 = A + (size_t)(bm + am1) * ldA + ak0;
    const float* Wp  = W + (size_t)(bn + wn)  * ldW + wk;
    const float4 z4 = make_float4(0.f, 0.f, 0.f, 0.f);

    float4 ra0 = av0 ? *(const float4*)Ap0 : z4;
    float4 ra1 = av1 ? *(const float4*)Ap1 : z4;
    float4 rw  = *(const float4*)Wp;

    for (int k0 = 0; k0 < K; k0 += BK) {
        As[ak0+0][am0] = ra0.x; As[ak0+1][am0] = ra0.y; As[ak0+2][am0] = ra0.z; As[ak0+3][am0] = ra0.w;
        As[ak0+0][am1] = ra1.x; As[ak0+1][am1] = ra1.y; As[ak0+2][am1] = ra1.z; As[ak0+3][am1] = ra1.w;
        Ws[wk+0][wn] = rw.x; Ws[wk+1][wn] = rw.y; Ws[wk+2][wn] = rw.z; Ws[wk+3][wn] = rw.w;
        __syncthreads();
        if (k0 + BK < K) {
            ra0 = av0 ? *(const float4*)(Ap0 + k0 + BK) : z4;
            ra1 = av1 ? *(const float4*)(Ap1 + k0 + BK) : z4;
            rw  = *(const float4*)(Wp + k0 + BK);
        }
#pragma unroll
        for (int kk = 0; kk < BK; kk++) {
            const float* ar = &As[kk][m0];
            ull a0 = *(const ull*)(ar + 0);
            ull a1 = *(const ull*)(ar + 2);
            ull a2 = *(const ull*)(ar + 4);
            ull a3 = *(const ull*)(ar + 6);
            float4 wq = *(const float4*)&Ws[kk][n0];
            ull w0 = pk(wq.x, wq.x), w1 = pk(wq.y, wq.y);
            ull w2 = pk(wq.z, wq.z), w3 = pk(wq.w, wq.w);
            ffma2(acc[0][0], a0, w0); ffma2(acc[0][1], a0, w1); ffma2(acc[0][2], a0, w2); ffma2(acc[0][3], a0, w3);
            ffma2(acc[1][0], a1, w0); ffma2(acc[1][1], a1, w1); ffma2(acc[1][2], a1, w2); ffma2(acc[1][3], a1, w3);
            ffma2(acc[2][0], a2, w0); ffma2(acc[2][1], a2, w1); ffma2(acc[2][2], a2, w2); ffma2(acc[2][3], a2, w3);
            ffma2(acc[3][0], a3, w0); ffma2(acc[3][1], a3, w1); ffma2(acc[3][2], a3, w2); ffma2(acc[3][3], a3, w3);
        }
        __syncthreads();
    }

#pragma unroll
    for (int i = 0; i < 4; i++) {
        float2 v0 = upk(acc[i][0]), v1 = upk(acc[i][1]);
        float2 v2 = upk(acc[i][2]), v3 = upk(acc[i][3]);
        int gm = bm + m0 + 2 * i;
        float* p0 = C + (size_t)gm * ldC + bn + n0;
        if (gm < M) {
            float4 o = make_float4(v0.x, v1.x, v2.x, v3.x);
            if (accum) { float4 d = *(const float4*)p0; o.x += d.x; o.y += d.y; o.z += d.z; o.w += d.w; }
            *(float4*)p0 = o;
        }
        if (gm + 1 < M) {
            float* p1 = p0 + ldC;
            float4 o = make_float4(v0.y, v1.y, v2.y, v3.y);
            if (accum) { float4 d = *(const float4*)p1; o.x += d.x; o.y += d.y; o.z += d.z; o.w += d.w; }
            *(float4*)p1 = o;
        }
    }
}

// ---------------- fused GRU step v2 ----------------
// 128 blocks x 128 threads. Block: all 64 b x 8 d-cols (blockIdx.x*8 ..+8).
// Warp w (0..3): d-pair {2w, 2w+1}. Lane l: dl = l&1 -> which d, bg = l>>1 (0..15).
// Thread: b rows {bg, bg+16, bg+32, bg+48} x 3 gates, accumulators packed over k.
//
// SMEM (dynamic, double buffered):
//   hs[2][64][260]  h tile (256 k-cols used, pitch 260 floats = 1040 B, 16B aligned)
//   ws[2][24][260]  w tile: rows = gate*8 + dloc
#define SK_PITCH 260
#define HS_BUF   (64 * SK_PITCH)          // 16640 floats
#define WS_BUF   (24 * SK_PITCH)          // 6240 floats
#define STEP_SMEM_FLOATS (2*HS_BUF + 2*WS_BUF)
#define STEP_SMEM_BYTES  (STEP_SMEM_FLOATS * 4)   // 183,040 B

__global__ __launch_bounds__(128) void step2_kernel(
    const float* __restrict__ h_in, float* __restrict__ h_out,
    const float* __restrict__ gi,   // [64][3072] slice for this t
    const float* __restrict__ gg,   // [64][1024] gate slice for this t
    const float* __restrict__ Whh,  // [3072][1024]
    const float* __restrict__ bih, const float* __restrict__ bhh)
{
    extern __shared__ float sm[];
    float* hs = sm;
    float* ws = sm + 2 * HS_BUF;

    const int tid = threadIdx.x;
    const int w   = tid >> 5;
    const int l   = tid & 31;
    const int dl  = l & 1;
    const int bg  = l >> 1;
    const int dloc = w * 2 + dl;           // 0..7
    const int bd0 = blockIdx.x * 8;
    const int d   = bd0 + dloc;

    const uint32_t hs_sm = (uint32_t)__cvta_generic_to_shared(hs);
    const uint32_t ws_sm = (uint32_t)__cvta_generic_to_shared(ws);

    // ---- staging helper (tile of 256 k at offset k0 into buffer buf) ----
    auto stage = [&](int buf, int k0) {
        uint32_t hb = hs_sm + (uint32_t)(buf * HS_BUF) * 4u;
        uint32_t wb = ws_sm + (uint32_t)(buf * WS_BUF) * 4u;
#pragma unroll
        for (int r = 0; r < 32; r++) {                 // 4096 granules / 128
            int i = tid + 128 * r;
            int row = i >> 6, g = i & 63;
            cpasync16(hb + (uint32_t)(row * SK_PITCH + g * 4) * 4u,
                      h_in + (size_t)row * 1024 + k0 + g * 4);
        }
#pragma unroll
        for (int r = 0; r < 12; r++) {                 // 1536 granules / 128
            int i = tid + 128 * r;
            int row = i >> 6, g = i & 63;
            int gate = row >> 3, dd = row & 7;
            cpasync16(wb + (uint32_t)(row * SK_PITCH + g * 4) * 4u,
                      Whh + (size_t)(gate * 1024 + bd0 + dd) * 1024 + k0 + g * 4);
        }
    };

    ull accx[12], accy[12];
#pragma unroll
    for (int i = 0; i < 12; i++) { accx[i] = 0ull; accy[i] = 0ull; }

    stage(0, 0); cpcommit();

    for (int t = 0; t < 4; t++) {
        if (t < 3) { stage((t + 1) & 1, (t + 1) * 256); cpcommit(); cpwait1(); }
        else       { cpwait0(); }
        __syncthreads();

        const float* hb = hs + (t & 1) * HS_BUF;
        const float* wb = ws + (t & 1) * WS_BUF;
        const float* hp0 = hb + (bg +  0) * SK_PITCH;
        const float* hp1 = hb + (bg + 16) * SK_PITCH;
        const float* hp2 = hb + (bg + 32) * SK_PITCH;
        const float* hp3 = hb + (bg + 48) * SK_PITCH;
        const float* wp0 = wb + (0 * 8 + dloc) * SK_PITCH;
        const float* wp1 = wb + (1 * 8 + dloc) * SK_PITCH;
        const float* wp2 = wb + (2 * 8 + dloc) * SK_PITCH;

#pragma unroll 8
        for (int kk = 0; kk < 256; kk += 4) {
            ulonglong2 wv0 = *(const ulonglong2*)(wp0 + kk);
            ulonglong2 wv1 = *(const ulonglong2*)(wp1 + kk);
            ulonglong2 wv2 = *(const ulonglong2*)(wp2 + kk);
            ulonglong2 h0 = *(const ulonglong2*)(hp0 + kk);
            ulonglong2 h1 = *(const ulonglong2*)(hp1 + kk);
            ulonglong2 h2 = *(const ulonglong2*)(hp2 + kk);
            ulonglong2 h3 = *(const ulonglong2*)(hp3 + kk);
            ffma2(accx[0],  h0.x, wv0.x); ffma2(accx[1],  h0.x, wv1.x); ffma2(accx[2],  h0.x, wv2.x);
            ffma2(accx[3],  h1.x, wv0.x); ffma2(accx[4],  h1.x, wv1.x); ffma2(accx[5],  h1.x, wv2.x);
            ffma2(accx[6],  h2.x, wv0.x); ffma2(accx[7],  h2.x, wv1.x); ffma2(accx[8],  h2.x, wv2.x);
            ffma2(accx[9],  h3.x, wv0.x); ffma2(accx[10], h3.x, wv1.x); ffma2(accx[11], h3.x, wv2.x);
            ffma2(accy[0],  h0.y, wv0.y); ffma2(accy[1],  h0.y, wv1.y); ffma2(accy[2],  h0.y, wv2.y);
            ffma2(accy[3],  h1.y, wv0.y); ffma2(accy[4],  h1.y, wv1.y); ffma2(accy[5],  h1.y, wv2.y);
            ffma2(accy[6],  h2.y, wv0.y); ffma2(accy[7],  h2.y, wv1.y); ffma2(accy[8],  h2.y, wv2.y);
            ffma2(accy[9],  h3.y, wv0.y); ffma2(accy[10], h3.y, wv1.y); ffma2(accy[11], h3.y, wv2.y);
        }
        __syncthreads();
    }

    // ---- epilogue: 4 (b, d) outputs per thread ----
    const float bir = bih[d], biz = bih[1024 + d], bin = bih[2048 + d];
    const float bhr = bhh[d], bhz = bhh[1024 + d], bhn = bhh[2048 + d];
#pragma unroll
    for (int i = 0; i < 4; i++) {
        int b = bg + 16 * i;
        float dr = sum2(accx[i*3+0]) + sum2(accy[i*3+0]);
        float dz = sum2(accx[i*3+1]) + sum2(accy[i*3+1]);
        float dn = sum2(accx[i*3+2]) + sum2(accy[i*3+2]);
        float gir = gi[b * 3072 + d]        + bir;
        float giz = gi[b * 3072 + 1024 + d] + biz;
        float gin = gi[b * 3072 + 2048 + d] + bin;
        float r = sigf(gir + dr + bhr);
        float z = sigf(giz + dz + bhz);
        float n = tanhfast(gin + r * (dn + bhn));
        float hp = h_in[b * 1024 + d];
        float hatt = (1.f - z) * n + z * hp;
        float G = gg[b * 1024 + d];
        h_out[b * 1024 + d] = G * hatt + (1.f - G) * hp;
    }
}

// ---------------- elementwise kernels ----------------
__global__ void feat3_kernel(const float* __restrict__ c, const float* __restrict__ x,
                             const float* __restrict__ y, float* __restrict__ FA,
                             float* __restrict__ FB, float* __restrict__ FC)
{
    int i = blockIdx.x * 256 + threadIdx.x;
    int bc = ((i >> 8) & 63) * 256 + (i & 255);
    float4 cv = ((const float4*)c)[i];
    float4 xv = ((const float4*)x)[bc];
    float4 yv = ((const float4*)y)[bc];
    ((float4*)FA)[i] = make_float4(cv.x*xv.x, cv.y*xv.y, cv.z*xv.z, cv.w*xv.w);
    ((float4*)FB)[i] = make_float4(fabsf(cv.x-xv.x), fabsf(cv.y-xv.y), fabsf(cv.z-xv.z), fabsf(cv.w-xv.w));
    ((float4*)FC)[i] = make_float4(cv.x*yv.x, cv.y*yv.y, cv.z*yv.z, cv.w*yv.w);
}

__global__ void addrow_kernel(const float* __restrict__ S0, const float* __restrict__ rc,
                              float* __restrict__ S)
{
    int i = blockIdx.x * 256 + threadIdx.x;
    int bc = ((i >> 8) & 63) * 256 + (i & 255);
    float4 a = ((const float4*)S0)[i];
    float4 r = ((const float4*)rc)[bc];
    ((float4*)S)[i] = make_float4(a.x+r.x, a.y+r.y, a.z+r.z, a.w+r.w);
}

__global__ void tanh_kernel(float* __restrict__ S)
{
    int i = blockIdx.x * 256 + threadIdx.x;
    float4 v = ((float4*)S)[i];
    ((float4*)S)[i] = make_float4(tanhfast(v.x), tanhfast(v.y), tanhfast(v.z), tanhfast(v.w));
}

__global__ void sigbias_kernel(float* __restrict__ G, const float* __restrict__ bias)
{
    int i = blockIdx.x * 256 + threadIdx.x;
    float4 b = ((const float4*)bias)[i & 255];
    float4 v = ((float4*)G)[i];
    ((float4*)G)[i] = make_float4(sigf(v.x+b.x), sigf(v.y+b.y), sigf(v.z+b.z), sigf(v.w+b.w));
}

__global__ void rowbias_kernel(float* __restrict__ rc, const float* __restrict__ bias)
{
    int i = blockIdx.x * 256 + threadIdx.x;
    float4 b = ((const float4*)bias)[i & 255];
    float4 v = ((float4*)rc)[i];
    ((float4*)rc)[i] = make_float4(v.x+b.x, v.y+b.y, v.z+b.z, v.w+b.w);
}

__global__ void zero_kernel(float* __restrict__ p)
{
    int i = blockIdx.x * 256 + threadIdx.x;
    ((float4*)p)[i] = make_float4(0.f, 0.f, 0.f, 0.f);
}

__global__ void gruew_kernel(const float* __restrict__ gi, const float* __restrict__ gh,
                             const float* __restrict__ h,  const float* __restrict__ bih,
                             const float* __restrict__ bhh, float* __restrict__ out)
{
    int i = blockIdx.x * 256 + threadIdx.x;
    int b = i >> 10, d = i & 1023;
    float gir = gi[b*3072 + d]        + bih[d];
    float giz = gi[b*3072 + 1024 + d] + bih[1024 + d];
    float gin = gi[b*3072 + 2048 + d] + bih[2048 + d];
    float ghr = gh[b*3072 + d]        + bhh[d];
    float ghz = gh[b*3072 + 1024 + d] + bhh[1024 + d];
    float ghn = gh[b*3072 + 2048 + d] + bhh[2048 + d];
    float r = sigf(gir + ghr);
    float z = sigf(giz + ghz);
    float n = tanhfast(gin + r * ghn);
    out[i] = (1.f - z) * n + z * h[i];
}

// ---------------- host orchestration ----------------
static void gemm(const float* A, int ldA, const float* W, int ldW,
                 float* C, int ldC, int M, int N, int K, int accum)
{
    dim3 g(N / BN, (M + BM - 1) / BM);
    gemm_kernel<<<g, 256>>>(A, ldA, W, ldW, C, ldC, M, K, accum);
}

extern "C" void kernel_launch(void* const* d_in, const int* in_sizes, int n_in,
                              void* d_out, int out_size)
{
    const float* c    = (const float*)d_in[0];
    const float* q    = (const float*)d_in[1];
    const float* Wb   = (const float*)d_in[2];
    const float* W1   = (const float*)d_in[3];
    const float* W1b  = (const float*)d_in[4];
    const float* W2   = (const float*)d_in[5];
    const float* W2b  = (const float*)d_in[6];
    const float* mWih = (const float*)d_in[7];
    const float* mWhh = (const float*)d_in[8];
    const float* mbih = (const float*)d_in[9];
    const float* mbhh = (const float*)d_in[10];
    const float* aWih = (const float*)d_in[11];
    const float* aWhh = (const float*)d_in[12];
    const float* abih = (const float*)d_in[13];
    const float* abhh = (const float*)d_in[14];

    static int smem_set = 0;
    if (!smem_set) {
        cudaFuncSetAttribute(step2_kernel, cudaFuncAttributeMaxDynamicSharedMemorySize,
                             STEP_SMEM_BYTES);
        smem_set = 1;
    }

    float *pFA, *pFB, *pFC, *pSinv, *pS, *pGI, *pWbq, *pWbm, *prc;
    float *ph0, *ph1, *pm, *pm2, *pgi, *pgh;
    cudaGetSymbolAddress((void**)&pFA,   g_FA);
    cudaGetSymbolAddress((void**)&pFB,   g_FB);
    cudaGetSymbolAddress((void**)&pFC,   g_FC);
    cudaGetSymbolAddress((void**)&pSinv, g_Sinv);
    cudaGetSymbolAddress((void**)&pS,    g_S);
    cudaGetSymbolAddress((void**)&pGI,   g_GI);
    cudaGetSymbolAddress((void**)&pWbq,  g_Wbq);
    cudaGetSymbolAddress((void**)&pWbm,  g_Wbm);
    cudaGetSymbolAddress((void**)&prc,   g_rc);
    cudaGetSymbolAddress((void**)&ph0,   g_h0);
    cudaGetSymbolAddress((void**)&ph1,   g_h1);
    cudaGetSymbolAddress((void**)&pm,    g_m);
    cudaGetSymbolAddress((void**)&pm2,   g_m2);
    cudaGetSymbolAddress((void**)&pgi,   g_gi);
    cudaGetSymbolAddress((void**)&pgh,   g_gh);

    const int GRID_TBD4 = (TB_ * D_ / 4) / 256;   // 8192
    const int GRID_BD4  = (B_ * D_ / 4) / 256;    // 64
    const int GRID_BD   = (B_ * D_) / 256;        // 256

    cudaMemcpyAsync(pm, q, (size_t)B_ * D_ * sizeof(float), cudaMemcpyDeviceToDevice);

    // episode-invariant precompute
    gemm(q, D_, Wb, D_, pWbq, D_, B_, D_, D_, 0);
    feat3_kernel<<<GRID_TBD4, 256>>>(c, q, pWbq, pFA, pFB, pFC);
    gemm(c,   D_, W1 + 0*D_, D9_, pSinv, D_, TB_, D_, D_, 0);
    gemm(pFA, D_, W1 + 3*D_, D9_, pSinv, D_, TB_, D_, D_, 1);
    gemm(pFB, D_, W1 + 5*D_, D9_, pSinv, D_, TB_, D_, D_, 1);
    gemm(pFC, D_, W1 + 7*D_, D9_, pSinv, D_, TB_, D_, D_, 1);
    gemm(c, D_, aWih, D_, pGI, D3_, TB_, D3_, D_, 0);

    float* mc = pm;
    float* mn = pm2;
    for (int ep = 0; ep < 2; ep++) {
        gemm(mc, D_, Wb, D_, pWbm, D_, B_, D_, D_, 0);
        gemm(mc, D_, W1 + 1*D_, D9_, prc, D_, B_, D_, D_, 0);
        gemm(q,  D_, W1 + 2*D_, D9_, prc, D_, B_, D_, D_, 1);
        rowbias_kernel<<<GRID_BD4, 256>>>(prc, W1b);
        feat3_kernel<<<GRID_TBD4, 256>>>(c, mc, pWbm, pFA, pFB, pFC);
        addrow_kernel<<<GRID_TBD4, 256>>>(pSinv, prc, pS);
        gemm(pFA, D_, W1 + 4*D_, D9_, pS, D_, TB_, D_, D_, 1);
        gemm(pFB, D_, W1 + 6*D_, D9_, pS, D_, TB_, D_, D_, 1);
        gemm(pFC, D_, W1 + 8*D_, D9_, pS, D_, TB_, D_, D_, 1);
        tanh_kernel<<<GRID_TBD4, 256>>>(pS);
        gemm(pS, D_, W2, D_, pFA, D_, TB_, D_, D_, 0);        // Gpre into FA
        sigbias_kernel<<<GRID_TBD4, 256>>>(pFA, W2b);         // G = sigmoid(Gpre + b2)

        zero_kernel<<<GRID_BD4, 256>>>(ph0);
        float* hin = ph0;
        float* hout = ph1;
        for (int t = 0; t < T_; t++) {
            step2_kernel<<<128, 128, STEP_SMEM_BYTES>>>(hin, hout,
                                      pGI + (size_t)t * B_ * D3_,
                                      pFA + (size_t)t * B_ * D_,
                                      aWhh, abih, abhh);
            float* tmp = hin; hin = hout; hout = tmp;
        }
        gemm(hin, D_, mWih, D_, pgi, D3_, B_, D3_, D_, 0);
        gemm(mc,  D_, mWhh, D_, pgh, D3_, B_, D3_, D_, 0);
        gruew_kernel<<<GRID_BD, 256>>>(pgi, pgh, mc, mbih, mbhh, mn);
        float* tmp = mc; mc = mn; mn = tmp;
    }

    cudaMemcpyAsync(d_out, mc, (size_t)B_ * D_ * sizeof(float), cudaMemcpyDeviceToDevice);
}

// round 13
// speedup vs baseline: 1.5492x; 1.3171x over previous
#include <cuda_runtime.h>
#include <cuda_bf16.h>
#include <stdint.h>

#define T_  128
#define B_  64
#define D_  1024
#define TB_ (T_*B_)
#define D3_ (3*D_)
#define D9_ (9*D_)

typedef unsigned long long ull;

// ---------------- static scratch (no allocation anywhere) ----------------
__device__ float g_FA[TB_*D_];
__device__ float g_FB[TB_*D_];
__device__ float g_FC[TB_*D_];
__device__ float g_Sinv[TB_*D_];
__device__ float g_S[TB_*D_];
__device__ float g_GI[TB_*D3_];
__device__ float g_Wbq[B_*D_];
__device__ float g_Wbm[B_*D_];
__device__ float g_rc[B_*D_];
__device__ float g_h0[B_*D_];
__device__ float g_h1[B_*D_];
__device__ float g_m[B_*D_];
__device__ float g_m2[B_*D_];
__device__ float g_gi[B_*D3_];
__device__ float g_gh[B_*D3_];

// bf16 split buffers
__device__ __nv_bfloat16 g_bAh[TB_*D_];
__device__ __nv_bfloat16 g_bAl[TB_*D_];
__device__ __nv_bfloat16 g_W1h[D_*D9_];
__device__ __nv_bfloat16 g_W1l[D_*D9_];
__device__ __nv_bfloat16 g_W2h[D_*D_];
__device__ __nv_bfloat16 g_W2l[D_*D_];
__device__ __nv_bfloat16 g_Wihh[D3_*D_];
__device__ __nv_bfloat16 g_Wihl[D3_*D_];

// ---------------- helpers ----------------
__device__ __forceinline__ void ffma2(ull& c, ull a, ull b) {
    asm("fma.rn.f32x2 %0, %1, %2, %0;" : "+l"(c) : "l"(a), "l"(b));
}
__device__ __forceinline__ ull pk(float lo, float hi) {
    ull r; asm("mov.b64 %0, {%1, %2};" : "=l"(r) : "f"(lo), "f"(hi)); return r;
}
__device__ __forceinline__ float2 upk(ull a) {
    float2 v; asm("mov.b64 {%0, %1}, %2;" : "=f"(v.x), "=f"(v.y) : "l"(a)); return v;
}
__device__ __forceinline__ float sum2(ull a) { float2 v = upk(a); return v.x + v.y; }
__device__ __forceinline__ float sigf(float x)     { return 1.f / (1.f + __expf(-x)); }
__device__ __forceinline__ float tanhfast(float x) { return 2.f / (1.f + __expf(-2.f*x)) - 1.f; }

__device__ __forceinline__ void cpasync16(uint32_t dst, const void* src) {
    asm volatile("cp.async.cg.shared.global [%0], [%1], 16;" :: "r"(dst), "l"(src));
}
__device__ __forceinline__ void cpcommit() { asm volatile("cp.async.commit_group;"); }
__device__ __forceinline__ void cpwait1()  { asm volatile("cp.async.wait_group 1;"); }
__device__ __forceinline__ void cpwait0()  { asm volatile("cp.async.wait_group 0;"); }

__device__ __forceinline__ void ldmx4(uint32_t addr, uint32_t* r) {
    asm volatile("ldmatrix.sync.aligned.m8n8.x4.shared.b16 {%0,%1,%2,%3}, [%4];"
                 : "=r"(r[0]), "=r"(r[1]), "=r"(r[2]), "=r"(r[3]) : "r"(addr));
}

#define MMA_BF16(c, a, b0, b1) \
    asm volatile("mma.sync.aligned.m16n8k16.row.col.f32.bf16.bf16.f32 " \
                 "{%0,%1,%2,%3}, {%4,%5,%6,%7}, {%8,%9}, {%0,%1,%2,%3};" \
                 : "+f"((c)[0]), "+f"((c)[1]), "+f"((c)[2]), "+f"((c)[3]) \
                 : "r"((a)[0]), "r"((a)[1]), "r"((a)[2]), "r"((a)[3]), \
                   "r"(b0), "r"(b1))

// ================= mma.sync split-bf16 GEMM =================
// C[M=8192, N] (+)= (Ah+Al) @ (Bh+Bl)^T, dropping the Al*Bl term.
// CTA: 128x128. 8 warps in 4(m) x 2(n); warp tile 32x64.
// K = 1024, chunks of KC=32, double-buffered cp.async.
// SMEM tile layout: [128 rows][pitch 40 bf16 = 80B] per operand.
#define KC      32
#define PITCHB  80u                       // bytes per row (40 bf16)
#define TILE_B  (128u * PITCHB)           // 10240 B
#define BUF_B   (4u * TILE_B)             // Ah|Al|Bh|Bl = 40960 B
#define TGS_SMEM (2 * BUF_B)              // 81920 B

__global__ __launch_bounds__(256) void tgemm_kernel(
    const __nv_bfloat16* __restrict__ Ah, const __nv_bfloat16* __restrict__ Al,
    const __nv_bfloat16* __restrict__ Bh, const __nv_bfloat16* __restrict__ Bl,
    int ldB, int kofs,
    float* __restrict__ C, int ldC, int accum)
{
    extern __shared__ __align__(16) char smraw[];
    const uint32_t sb = (uint32_t)__cvta_generic_to_shared(smraw);

    const int tid  = threadIdx.x;
    const int wid  = tid >> 5;
    const int lane = tid & 31;
    const int bm   = blockIdx.y * 128;
    const int bn   = blockIdx.x * 128;
    const int wm   = wid & 3;     // m warp row (32 rows)
    const int wn   = wid >> 2;    // n warp col (64 cols)

    float acc[2][8][4];
#pragma unroll
    for (int i = 0; i < 2; i++)
#pragma unroll
        for (int j = 0; j < 8; j++)
#pragma unroll
            for (int k = 0; k < 4; k++) acc[i][j][k] = 0.f;

    // stage one KC-chunk (k offset k0) into buffer buf. 2048 16B granules / 256 thr.
    auto stage = [&](int buf, int k0) {
        uint32_t base = sb + (uint32_t)buf * BUF_B;
#pragma unroll
        for (int r = 0; r < 8; r++) {
            int id   = tid + 256 * r;          // 0..2047
            int tile = id >> 9;                // 0..3
            int row  = (id >> 2) & 127;
            int g    = id & 3;                 // 16B granule within 64B row
            uint32_t daddr = base + (uint32_t)tile * TILE_B + (uint32_t)row * PITCHB + (uint32_t)g * 16u;
            const __nv_bfloat16* src;
            if      (tile == 0) src = Ah + (size_t)(bm + row) * 1024 + k0 + g * 8;
            else if (tile == 1) src = Al + (size_t)(bm + row) * 1024 + k0 + g * 8;
            else if (tile == 2) src = Bh + (size_t)(bn + row) * ldB + kofs + k0 + g * 8;
            else                src = Bl + (size_t)(bn + row) * ldB + kofs + k0 + g * 8;
            cpasync16(daddr, src);
        }
    };

    stage(0, 0); cpcommit();

    for (int ch = 0; ch < 1024 / KC; ch++) {
        if (ch + 1 < 1024 / KC) { stage((ch + 1) & 1, (ch + 1) * KC); cpcommit(); cpwait1(); }
        else                    { cpwait0(); }
        __syncthreads();

        uint32_t base = sb + (uint32_t)(ch & 1) * BUF_B;
#pragma unroll
        for (int ks = 0; ks < 2; ks++) {       // two k16 steps per chunk
            uint32_t ah[2][4], al[2][4], bh[4][4], bl[4][4];
#pragma unroll
            for (int tm = 0; tm < 2; tm++) {
                uint32_t row = (uint32_t)(wm * 32 + tm * 16 + (lane & 15));
                uint32_t addr = base + row * PITCHB + (uint32_t)(ks * 32) + (uint32_t)((lane >> 4) * 16);
                ldmx4(addr, ah[tm]);
                ldmx4(addr + TILE_B, al[tm]);
            }
#pragma unroll
            for (int tb = 0; tb < 4; tb++) {
                uint32_t rn = (uint32_t)(wn * 64 + tb * 16 + ((lane >> 4) << 3) + (lane & 7));
                uint32_t addr = base + 2u * TILE_B + rn * PITCHB + (uint32_t)(ks * 32) + (uint32_t)(((lane >> 3) & 1) * 16);
                ldmx4(addr, bh[tb]);
                ldmx4(addr + TILE_B, bl[tb]);
            }
#pragma unroll
            for (int tm = 0; tm < 2; tm++)
#pragma unroll
                for (int tn = 0; tn < 8; tn++) {
                    int tb = tn >> 1, s = (tn & 1) * 2;
                    MMA_BF16(acc[tm][tn], ah[tm], bh[tb][s], bh[tb][s + 1]);
                    MMA_BF16(acc[tm][tn], ah[tm], bl[tb][s], bl[tb][s + 1]);
                    MMA_BF16(acc[tm][tn], al[tm], bh[tb][s], bh[tb][s + 1]);
                }
        }
        __syncthreads();
    }

    // epilogue: c0,c1 -> (row lane/4, cols 2*(lane%4)+{0,1}); c2,c3 -> row+8
    const int r0 = bm + wm * 32 + (lane >> 2);
    const int cb = bn + wn * 64 + (lane & 3) * 2;
#pragma unroll
    for (int tm = 0; tm < 2; tm++)
#pragma unroll
        for (int tn = 0; tn < 8; tn++) {
            float* p0 = C + (size_t)(r0 + tm * 16) * ldC + cb + tn * 8;
            float* p1 = p0 + 8 * (size_t)ldC;
            if (accum) {
                float2 d0 = *(float2*)p0;
                d0.x += acc[tm][tn][0]; d0.y += acc[tm][tn][1];
                *(float2*)p0 = d0;
                float2 d1 = *(float2*)p1;
                d1.x += acc[tm][tn][2]; d1.y += acc[tm][tn][3];
                *(float2*)p1 = d1;
            } else {
                *(float2*)p0 = make_float2(acc[tm][tn][0], acc[tm][tn][1]);
                *(float2*)p1 = make_float2(acc[tm][tn][2], acc[tm][tn][3]);
            }
        }
}

// ---------------- fp32 split kernel: hi = bf16(x), lo = bf16(x - hi) ----------------
__global__ void split_kernel(const float* __restrict__ s, __nv_bfloat16* __restrict__ hi,
                             __nv_bfloat16* __restrict__ lo, int n4)
{
    int i = blockIdx.x * 256 + threadIdx.x;
    if (i >= n4) return;
    float4 v = ((const float4*)s)[i];
    __nv_bfloat16 hx = __float2bfloat16(v.x), hy = __float2bfloat16(v.y);
    __nv_bfloat16 hz = __float2bfloat16(v.z), hw = __float2bfloat16(v.w);
    __nv_bfloat16 lx = __float2bfloat16(v.x - __bfloat162float(hx));
    __nv_bfloat16 ly = __float2bfloat16(v.y - __bfloat162float(hy));
    __nv_bfloat16 lz = __float2bfloat16(v.z - __bfloat162float(hz));
    __nv_bfloat16 lw = __float2bfloat16(v.w - __bfloat162float(hw));
    ((__nv_bfloat162*)hi)[2*i]   = __nv_bfloat162(hx, hy);
    ((__nv_bfloat162*)hi)[2*i+1] = __nv_bfloat162(hz, hw);
    ((__nv_bfloat162*)lo)[2*i]   = __nv_bfloat162(lx, ly);
    ((__nv_bfloat162*)lo)[2*i+1] = __nv_bfloat162(lz, lw);
}

// ---------------- fp32 SGEMM (small M) : C[M,N] (+)= A[M,K] @ W[N,K]^T ----------------
#define BM 128
#define BN 64
#define BK 16

__global__ __launch_bounds__(256) void gemm_kernel(
    const float* __restrict__ A, int ldA,
    const float* __restrict__ W, int ldW,
    float* __restrict__ C, int ldC,
    int M, int K, int accum)
{
    __shared__ float As[BK][BM+4];
    __shared__ float Ws[BK][BN+4];
    const int tid = threadIdx.x;
    const int bm = blockIdx.y * BM;
    const int bn = blockIdx.x * BN;
    const int tx = tid & 15, ty = tid >> 4;
    const int m0 = ty << 3, n0 = tx << 2;

    ull acc[4][4];
#pragma unroll
    for (int i = 0; i < 4; i++)
#pragma unroll
        for (int j = 0; j < 4; j++) acc[i][j] = 0ull;

    const int am0 = tid >> 2, ak0 = (tid & 3) << 2;
    const int am1 = am0 + 64;
    const int wn  = tid >> 2, wk  = ak0;
    const bool av0 = (bm + am0) < M;
    const bool av1 = (bm + am1) < M;
    const float* Ap0 = A + (size_t)(bm + am0) * ldA + ak0;
    const float* Ap1 = A + (size_t)(bm + am1) * ldA + ak0;
    const float* Wp  = W + (size_t)(bn + wn)  * ldW + wk;
    const float4 z4 = make_float4(0.f, 0.f, 0.f, 0.f);

    float4 ra0 = av0 ? *(const float4*)Ap0 : z4;
    float4 ra1 = av1 ? *(const float4*)Ap1 : z4;
    float4 rw  = *(const float4*)Wp;

    for (int k0 = 0; k0 < K; k0 += BK) {
        As[ak0+0][am0] = ra0.x; As[ak0+1][am0] = ra0.y; As[ak0+2][am0] = ra0.z; As[ak0+3][am0] = ra0.w;
        As[ak0+0][am1] = ra1.x; As[ak0+1][am1] = ra1.y; As[ak0+2][am1] = ra1.z; As[ak0+3][am1] = ra1.w;
        Ws[wk+0][wn] = rw.x; Ws[wk+1][wn] = rw.y; Ws[wk+2][wn] = rw.z; Ws[wk+3][wn] = rw.w;
        __syncthreads();
        if (k0 + BK < K) {
            ra0 = av0 ? *(const float4*)(Ap0 + k0 + BK) : z4;
            ra1 = av1 ? *(const float4*)(Ap1 + k0 + BK) : z4;
            rw  = *(const float4*)(Wp + k0 + BK);
        }
#pragma unroll
        for (int kk = 0; kk < BK; kk++) {
            const float* ar = &As[kk][m0];
            ull a0 = *(const ull*)(ar + 0);
            ull a1 = *(const ull*)(ar + 2);
            ull a2 = *(const ull*)(ar + 4);
            ull a3 = *(const ull*)(ar + 6);
            float4 wq = *(const float4*)&Ws[kk][n0];
            ull w0 = pk(wq.x, wq.x), w1 = pk(wq.y, wq.y);
            ull w2 = pk(wq.z, wq.z), w3 = pk(wq.w, wq.w);
            ffma2(acc[0][0], a0, w0); ffma2(acc[0][1], a0, w1); ffma2(acc[0][2], a0, w2); ffma2(acc[0][3], a0, w3);
            ffma2(acc[1][0], a1, w0); ffma2(acc[1][1], a1, w1); ffma2(acc[1][2], a1, w2); ffma2(acc[1][3], a1, w3);
            ffma2(acc[2][0], a2, w0); ffma2(acc[2][1], a2, w1); ffma2(acc[2][2], a2, w2); ffma2(acc[2][3], a2, w3);
            ffma2(acc[3][0], a3, w0); ffma2(acc[3][1], a3, w1); ffma2(acc[3][2], a3, w2); ffma2(acc[3][3], a3, w3);
        }
        __syncthreads();
    }

#pragma unroll
    for (int i = 0; i < 4; i++) {
        float2 v0 = upk(acc[i][0]), v1 = upk(acc[i][1]);
        float2 v2 = upk(acc[i][2]), v3 = upk(acc[i][3]);
        int gm = bm + m0 + 2 * i;
        float* p0 = C + (size_t)gm * ldC + bn + n0;
        if (gm < M) {
            float4 o = make_float4(v0.x, v1.x, v2.x, v3.x);
            if (accum) { float4 d = *(const float4*)p0; o.x += d.x; o.y += d.y; o.z += d.z; o.w += d.w; }
            *(float4*)p0 = o;
        }
        if (gm + 1 < M) {
            float* p1 = p0 + ldC;
            float4 o = make_float4(v0.y, v1.y, v2.y, v3.y);
            if (accum) { float4 d = *(const float4*)p1; o.x += d.x; o.y += d.y; o.z += d.z; o.w += d.w; }
            *(float4*)p1 = o;
        }
    }
}

// ---------------- fused GRU step (unchanged from R11, passing) ----------------
#define SK_PITCH 260
#define HS_BUF   (64 * SK_PITCH)
#define WS_BUF   (24 * SK_PITCH)
#define STEP_SMEM_BYTES ((2*HS_BUF + 2*WS_BUF) * 4)

__global__ __launch_bounds__(128) void step2_kernel(
    const float* __restrict__ h_in, float* __restrict__ h_out,
    const float* __restrict__ gi, const float* __restrict__ gg,
    const float* __restrict__ Whh,
    const float* __restrict__ bih, const float* __restrict__ bhh)
{
    extern __shared__ float sm[];
    float* hs = sm;
    float* ws = sm + 2 * HS_BUF;

    const int tid = threadIdx.x;
    const int w   = tid >> 5;
    const int l   = tid & 31;
    const int dl  = l & 1;
    const int bg  = l >> 1;
    const int dloc = w * 2 + dl;
    const int bd0 = blockIdx.x * 8;
    const int d   = bd0 + dloc;

    const uint32_t hs_sm = (uint32_t)__cvta_generic_to_shared(hs);
    const uint32_t ws_sm = (uint32_t)__cvta_generic_to_shared(ws);

    auto stage = [&](int buf, int k0) {
        uint32_t hb = hs_sm + (uint32_t)(buf * HS_BUF) * 4u;
        uint32_t wb = ws_sm + (uint32_t)(buf * WS_BUF) * 4u;
#pragma unroll
        for (int r = 0; r < 32; r++) {
            int i = tid + 128 * r;
            int row = i >> 6, g = i & 63;
            cpasync16(hb + (uint32_t)(row * SK_PITCH + g * 4) * 4u,
                      h_in + (size_t)row * 1024 + k0 + g * 4);
        }
#pragma unroll
        for (int r = 0; r < 12; r++) {
            int i = tid + 128 * r;
            int row = i >> 6, g = i & 63;
            int gate = row >> 3, dd = row & 7;
            cpasync16(wb + (uint32_t)(row * SK_PITCH + g * 4) * 4u,
                      Whh + (size_t)(gate * 1024 + bd0 + dd) * 1024 + k0 + g * 4);
        }
    };

    ull accx[12], accy[12];
#pragma unroll
    for (int i = 0; i < 12; i++) { accx[i] = 0ull; accy[i] = 0ull; }

    stage(0, 0); cpcommit();

    for (int t = 0; t < 4; t++) {
        if (t < 3) { stage((t + 1) & 1, (t + 1) * 256); cpcommit(); cpwait1(); }
        else       { cpwait0(); }
        __syncthreads();

        const float* hb = hs + (t & 1) * HS_BUF;
        const float* wb = ws + (t & 1) * WS_BUF;
        const float* hp0 = hb + (bg +  0) * SK_PITCH;
        const float* hp1 = hb + (bg + 16) * SK_PITCH;
        const float* hp2 = hb + (bg + 32) * SK_PITCH;
        const float* hp3 = hb + (bg + 48) * SK_PITCH;
        const float* wp0 = wb + (0 * 8 + dloc) * SK_PITCH;
        const float* wp1 = wb + (1 * 8 + dloc) * SK_PITCH;
        const float* wp2 = wb + (2 * 8 + dloc) * SK_PITCH;

#pragma unroll 8
        for (int kk = 0; kk < 256; kk += 4) {
            ulonglong2 wv0 = *(const ulonglong2*)(wp0 + kk);
            ulonglong2 wv1 = *(const ulonglong2*)(wp1 + kk);
            ulonglong2 wv2 = *(const ulonglong2*)(wp2 + kk);
            ulonglong2 h0 = *(const ulonglong2*)(hp0 + kk);
            ulonglong2 h1 = *(const ulonglong2*)(hp1 + kk);
            ulonglong2 h2 = *(const ulonglong2*)(hp2 + kk);
            ulonglong2 h3 = *(const ulonglong2*)(hp3 + kk);
            ffma2(accx[0],  h0.x, wv0.x); ffma2(accx[1],  h0.x, wv1.x); ffma2(accx[2],  h0.x, wv2.x);
            ffma2(accx[3],  h1.x, wv0.x); ffma2(accx[4],  h1.x, wv1.x); ffma2(accx[5],  h1.x, wv2.x);
            ffma2(accx[6],  h2.x, wv0.x); ffma2(accx[7],  h2.x, wv1.x); ffma2(accx[8],  h2.x, wv2.x);
            ffma2(accx[9],  h3.x, wv0.x); ffma2(accx[10], h3.x, wv1.x); ffma2(accx[11], h3.x, wv2.x);
            ffma2(accy[0],  h0.y, wv0.y); ffma2(accy[1],  h0.y, wv1.y); ffma2(accy[2],  h0.y, wv2.y);
            ffma2(accy[3],  h1.y, wv0.y); ffma2(accy[4],  h1.y, wv1.y); ffma2(accy[5],  h1.y, wv2.y);
            ffma2(accy[6],  h2.y, wv0.y); ffma2(accy[7],  h2.y, wv1.y); ffma2(accy[8],  h2.y, wv2.y);
            ffma2(accy[9],  h3.y, wv0.y); ffma2(accy[10], h3.y, wv1.y); ffma2(accy[11], h3.y, wv2.y);
        }
        __syncthreads();
    }

    const float bir = bih[d], biz = bih[1024 + d], bin = bih[2048 + d];
    const float bhr = bhh[d], bhz = bhh[1024 + d], bhn = bhh[2048 + d];
#pragma unroll
    for (int i = 0; i < 4; i++) {
        int b = bg + 16 * i;
        float dr = sum2(accx[i*3+0]) + sum2(accy[i*3+0]);
        float dz = sum2(accx[i*3+1]) + sum2(accy[i*3+1]);
        float dn = sum2(accx[i*3+2]) + sum2(accy[i*3+2]);
        float gir = gi[b * 3072 + d]        + bir;
        float giz = gi[b * 3072 + 1024 + d] + biz;
        float gin = gi[b * 3072 + 2048 + d] + bin;
        float r = sigf(gir + dr + bhr);
        float z = sigf(giz + dz + bhz);
        float n = tanhfast(gin + r * (dn + bhn));
        float hp = h_in[b * 1024 + d];
        float hatt = (1.f - z) * n + z * hp;
        float G = gg[b * 1024 + d];
        h_out[b * 1024 + d] = G * hatt + (1.f - G) * hp;
    }
}

// ---------------- elementwise kernels ----------------
__global__ void feat3_kernel(const float* __restrict__ c, const float* __restrict__ x,
                             const float* __restrict__ y, float* __restrict__ FA,
                             float* __restrict__ FB, float* __restrict__ FC)
{
    int i = blockIdx.x * 256 + threadIdx.x;
    int bc = ((i >> 8) & 63) * 256 + (i & 255);
    float4 cv = ((const float4*)c)[i];
    float4 xv = ((const float4*)x)[bc];
    float4 yv = ((const float4*)y)[bc];
    ((float4*)FA)[i] = make_float4(cv.x*xv.x, cv.y*xv.y, cv.z*xv.z, cv.w*xv.w);
    ((float4*)FB)[i] = make_float4(fabsf(cv.x-xv.x), fabsf(cv.y-xv.y), fabsf(cv.z-xv.z), fabsf(cv.w-xv.w));
    ((float4*)FC)[i] = make_float4(cv.x*yv.x, cv.y*yv.y, cv.z*yv.z, cv.w*yv.w);
}

__global__ void addrow_kernel(const float* __restrict__ S0, const float* __restrict__ rc,
                              float* __restrict__ S)
{
    int i = blockIdx.x * 256 + threadIdx.x;
    int bc = ((i >> 8) & 63) * 256 + (i & 255);
    float4 a = ((const float4*)S0)[i];
    float4 r = ((const float4*)rc)[bc];
    ((float4*)S)[i] = make_float4(a.x+r.x, a.y+r.y, a.z+r.z, a.w+r.w);
}

__global__ void tanh_kernel(float* __restrict__ S)
{
    int i = blockIdx.x * 256 + threadIdx.x;
    float4 v = ((float4*)S)[i];
    ((float4*)S)[i] = make_float4(tanhfast(v.x), tanhfast(v.y), tanhfast(v.z), tanhfast(v.w));
}

__global__ void sigbias_kernel(float* __restrict__ G, const float* __restrict__ bias)
{
    int i = blockIdx.x * 256 + threadIdx.x;
    float4 b = ((const float4*)bias)[i & 255];
    float4 v = ((float4*)G)[i];
    ((float4*)G)[i] = make_float4(sigf(v.x+b.x), sigf(v.y+b.y), sigf(v.z+b.z), sigf(v.w+b.w));
}

__global__ void rowbias_kernel(float* __restrict__ rc, const float* __restrict__ bias)
{
    int i = blockIdx.x * 256 + threadIdx.x;
    float4 b = ((const float4*)bias)[i & 255];
    float4 v = ((float4*)rc)[i];
    ((float4*)rc)[i] = make_float4(v.x+b.x, v.y+b.y, v.z+b.z, v.w+b.w);
}

__global__ void zero_kernel(float* __restrict__ p)
{
    int i = blockIdx.x * 256 + threadIdx.x;
    ((float4*)p)[i] = make_float4(0.f, 0.f, 0.f, 0.f);
}

__global__ void gruew_kernel(const float* __restrict__ gi, const float* __restrict__ gh,
                             const float* __restrict__ h,  const float* __restrict__ bih,
                             const float* __restrict__ bhh, float* __restrict__ out)
{
    int i = blockIdx.x * 256 + threadIdx.x;
    int b = i >> 10, d = i & 1023;
    float gir = gi[b*3072 + d]        + bih[d];
    float giz = gi[b*3072 + 1024 + d] + bih[1024 + d];
    float gin = gi[b*3072 + 2048 + d] + bih[2048 + d];
    float ghr = gh[b*3072 + d]        + bhh[d];
    float ghz = gh[b*3072 + 1024 + d] + bhh[1024 + d];
    float ghn = gh[b*3072 + 2048 + d] + bhh[2048 + d];
    float r = sigf(gir + ghr);
    float z = sigf(giz + ghz);
    float n = tanhfast(gin + r * ghn);
    out[i] = (1.f - z) * n + z * h[i];
}

// ---------------- host orchestration ----------------
static void gemm(const float* A, int ldA, const float* W, int ldW,
                 float* C, int ldC, int M, int N, int K, int accum)
{
    dim3 g(N / BN, (M + BM - 1) / BM);
    gemm_kernel<<<g, 256>>>(A, ldA, W, ldW, C, ldC, M, K, accum);
}

static void tgemm(const __nv_bfloat16* Ah, const __nv_bfloat16* Al,
                  const __nv_bfloat16* Bh, const __nv_bfloat16* Bl,
                  int ldB, int kofs, float* C, int ldC, int N, int accum)
{
    dim3 g(N / 128, TB_ / 128);
    tgemm_kernel<<<g, 256, TGS_SMEM>>>(Ah, Al, Bh, Bl, ldB, kofs, C, ldC, accum);
}

extern "C" void kernel_launch(void* const* d_in, const int* in_sizes, int n_in,
                              void* d_out, int out_size)
{
    const float* c    = (const float*)d_in[0];
    const float* q    = (const float*)d_in[1];
    const float* Wb   = (const float*)d_in[2];
    const float* W1   = (const float*)d_in[3];
    const float* W1b  = (const float*)d_in[4];
    const float* W2   = (const float*)d_in[5];
    const float* W2b  = (const float*)d_in[6];
    const float* mWih = (const float*)d_in[7];
    const float* mWhh = (const float*)d_in[8];
    const float* mbih = (const float*)d_in[9];
    const float* mbhh = (const float*)d_in[10];
    const float* aWih = (const float*)d_in[11];
    const float* aWhh = (const float*)d_in[12];
    const float* abih = (const float*)d_in[13];
    const float* abhh = (const float*)d_in[14];

    cudaFuncSetAttribute(step2_kernel, cudaFuncAttributeMaxDynamicSharedMemorySize, STEP_SMEM_BYTES);
    cudaFuncSetAttribute(tgemm_kernel, cudaFuncAttributeMaxDynamicSharedMemorySize, TGS_SMEM);

    float *pFA, *pFB, *pFC, *pSinv, *pS, *pGI, *pWbq, *pWbm, *prc;
    float *ph0, *ph1, *pm, *pm2, *pgi, *pgh;
    __nv_bfloat16 *bAh, *bAl, *bW1h, *bW1l, *bW2h, *bW2l, *bWihh, *bWihl;
    cudaGetSymbolAddress((void**)&pFA,   g_FA);
    cudaGetSymbolAddress((void**)&pFB,   g_FB);
    cudaGetSymbolAddress((void**)&pFC,   g_FC);
    cudaGetSymbolAddress((void**)&pSinv, g_Sinv);
    cudaGetSymbolAddress((void**)&pS,    g_S);
    cudaGetSymbolAddress((void**)&pGI,   g_GI);
    cudaGetSymbolAddress((void**)&pWbq,  g_Wbq);
    cudaGetSymbolAddress((void**)&pWbm,  g_Wbm);
    cudaGetSymbolAddress((void**)&prc,   g_rc);
    cudaGetSymbolAddress((void**)&ph0,   g_h0);
    cudaGetSymbolAddress((void**)&ph1,   g_h1);
    cudaGetSymbolAddress((void**)&pm,    g_m);
    cudaGetSymbolAddress((void**)&pm2,   g_m2);
    cudaGetSymbolAddress((void**)&pgi,   g_gi);
    cudaGetSymbolAddress((void**)&pgh,   g_gh);
    cudaGetSymbolAddress((void**)&bAh,   g_bAh);
    cudaGetSymbolAddress((void**)&bAl,   g_bAl);
    cudaGetSymbolAddress((void**)&bW1h,  g_W1h);
    cudaGetSymbolAddress((void**)&bW1l,  g_W1l);
    cudaGetSymbolAddress((void**)&bW2h,  g_W2h);
    cudaGetSymbolAddress((void**)&bW2l,  g_W2l);
    cudaGetSymbolAddress((void**)&bWihh, g_Wihh);
    cudaGetSymbolAddress((void**)&bWihl, g_Wihl);

    const int GRID_TBD4 = (TB_ * D_ / 4) / 256;   // 8192
    const int GRID_BD4  = (B_ * D_ / 4) / 256;
    const int GRID_BD   = (B_ * D_) / 256;

    cudaMemcpyAsync(pm, q, (size_t)B_ * D_ * sizeof(float), cudaMemcpyDeviceToDevice);

    // weight splits (every launch; deterministic)
    split_kernel<<<(D_*D9_/4)/256, 256>>>(W1, bW1h, bW1l, D_*D9_/4);
    split_kernel<<<(D_*D_/4)/256, 256>>>(W2, bW2h, bW2l, D_*D_/4);
    split_kernel<<<(D3_*D_/4)/256, 256>>>(aWih, bWihh, bWihl, D3_*D_/4);

    // episode-invariant precompute
    gemm(q, D_, Wb, D_, pWbq, D_, B_, D_, D_, 0);
    feat3_kernel<<<GRID_TBD4, 256>>>(c, q, pWbq, pFA, pFB, pFC);

    split_kernel<<<GRID_TBD4, 256>>>(c, bAh, bAl, TB_*D_/4);
    tgemm(bAh, bAl, bW1h, bW1l, D9_, 0*D_, pSinv, D_, D_, 0);        // c @ V0^T
    tgemm(bAh, bAl, bWihh, bWihl, D_, 0, pGI, D3_, D3_, 0);          // gi_att all t

    split_kernel<<<GRID_TBD4, 256>>>(pFA, bAh, bAl, TB_*D_/4);
    tgemm(bAh, bAl, bW1h, bW1l, D9_, 3*D_, pSinv, D_, D_, 1);        // + c*q @ V3^T
    split_kernel<<<GRID_TBD4, 256>>>(pFB, bAh, bAl, TB_*D_/4);
    tgemm(bAh, bAl, bW1h, bW1l, D9_, 5*D_, pSinv, D_, D_, 1);        // + |c-q| @ V5^T
    split_kernel<<<GRID_TBD4, 256>>>(pFC, bAh, bAl, TB_*D_/4);
    tgemm(bAh, bAl, bW1h, bW1l, D9_, 7*D_, pSinv, D_, D_, 1);        // + c*Wbq @ V7^T

    float* mc = pm;
    float* mn = pm2;
    for (int ep = 0; ep < 2; ep++) {
        gemm(mc, D_, Wb, D_, pWbm, D_, B_, D_, D_, 0);
        gemm(mc, D_, W1 + 1*D_, D9_, prc, D_, B_, D_, D_, 0);
        gemm(q,  D_, W1 + 2*D_, D9_, prc, D_, B_, D_, D_, 1);
        rowbias_kernel<<<GRID_BD4, 256>>>(prc, W1b);
        feat3_kernel<<<GRID_TBD4, 256>>>(c, mc, pWbm, pFA, pFB, pFC);
        addrow_kernel<<<GRID_TBD4, 256>>>(pSinv, prc, pS);

        split_kernel<<<GRID_TBD4, 256>>>(pFA, bAh, bAl, TB_*D_/4);
        tgemm(bAh, bAl, bW1h, bW1l, D9_, 4*D_, pS, D_, D_, 1);       // + c*m @ V4^T
        split_kernel<<<GRID_TBD4, 256>>>(pFB, bAh, bAl, TB_*D_/4);
        tgemm(bAh, bAl, bW1h, bW1l, D9_, 6*D_, pS, D_, D_, 1);       // + |c-m| @ V6^T
        split_kernel<<<GRID_TBD4, 256>>>(pFC, bAh, bAl, TB_*D_/4);
        tgemm(bAh, bAl, bW1h, bW1l, D9_, 8*D_, pS, D_, D_, 1);       // + c*Wbm @ V8^T

        tanh_kernel<<<GRID_TBD4, 256>>>(pS);
        split_kernel<<<GRID_TBD4, 256>>>(pS, bAh, bAl, TB_*D_/4);
        tgemm(bAh, bAl, bW2h, bW2l, D_, 0, pFA, D_, D_, 0);          // Gpre into FA
        sigbias_kernel<<<GRID_TBD4, 256>>>(pFA, W2b);                // G

        zero_kernel<<<GRID_BD4, 256>>>(ph0);
        float* hin = ph0;
        float* hout = ph1;
        for (int t = 0; t < T_; t++) {
            step2_kernel<<<128, 128, STEP_SMEM_BYTES>>>(hin, hout,
                                      pGI + (size_t)t * B_ * D3_,
                                      pFA + (size_t)t * B_ * D_,
                                      aWhh, abih, abhh);
            float* tmp = hin; hin = hout; hout = tmp;
        }
        gemm(hin, D_, mWih, D_, pgi, D3_, B_, D3_, D_, 0);
        gemm(mc,  D_, mWhh, D_, pgh, D3_, B_, D3_, D_, 0);
        gruew_kernel<<<GRID_BD, 256>>>(pgi, pgh, mc, mbih, mbhh, mn);
        float* tmp = mc; mc = mn; mn = tmp;
    }

    cudaMemcpyAsync(d_out, mc, (size_t)B_ * D_ * sizeof(float), cudaMemcpyDeviceToDevice);
}

// round 14
// speedup vs baseline: 1.9580x; 1.2639x over previous
#include <cuda_runtime.h>
#include <cuda_bf16.h>
#include <stdint.h>

#define T_  128
#define B_  64
#define D_  1024
#define TB_ (T_*B_)
#define D3_ (3*D_)
#define D9_ (9*D_)

typedef unsigned long long ull;

// ---------------- static scratch (no allocation anywhere) ----------------
__device__ float g_FAg[TB_*D_];      // fp32 gate buffer G (tgemm W2 output)
__device__ float g_Sinv[TB_*D_];
__device__ float g_S[TB_*D_];
__device__ float g_GI[TB_*D3_];
__device__ float g_Wbq[B_*D_];
__device__ float g_Wbm[B_*D_];
__device__ float g_rc[B_*D_];
__device__ float g_rcq[B_*D_];
__device__ float g_h0[B_*D_];
__device__ float g_h1[B_*D_];
__device__ float g_m[B_*D_];
__device__ float g_m2[B_*D_];
__device__ float g_gi[B_*D3_];
__device__ float g_gh[B_*D3_];
__device__ int   g_barrier;

// bf16 split buffers
__device__ __nv_bfloat16 g_bAh[TB_*D_];
__device__ __nv_bfloat16 g_bAl[TB_*D_];
__device__ __nv_bfloat16 g_FAh[TB_*D_];
__device__ __nv_bfloat16 g_FAl[TB_*D_];
__device__ __nv_bfloat16 g_FBh[TB_*D_];
__device__ __nv_bfloat16 g_FBl[TB_*D_];
__device__ __nv_bfloat16 g_FCh[TB_*D_];
__device__ __nv_bfloat16 g_FCl[TB_*D_];
__device__ __nv_bfloat16 g_W1h[D_*D9_];
__device__ __nv_bfloat16 g_W1l[D_*D9_];
__device__ __nv_bfloat16 g_W2h[D_*D_];
__device__ __nv_bfloat16 g_W2l[D_*D_];
__device__ __nv_bfloat16 g_Wihh[D3_*D_];
__device__ __nv_bfloat16 g_Wihl[D3_*D_];

// ---------------- helpers ----------------
__device__ __forceinline__ void ffma2(ull& c, ull a, ull b) {
    asm("fma.rn.f32x2 %0, %1, %2, %0;" : "+l"(c) : "l"(a), "l"(b));
}
__device__ __forceinline__ ull pk(float lo, float hi) {
    ull r; asm("mov.b64 %0, {%1, %2};" : "=l"(r) : "f"(lo), "f"(hi)); return r;
}
__device__ __forceinline__ float2 upk(ull a) {
    float2 v; asm("mov.b64 {%0, %1}, %2;" : "=f"(v.x), "=f"(v.y) : "l"(a)); return v;
}
__device__ __forceinline__ float sum2(ull a) { float2 v = upk(a); return v.x + v.y; }
__device__ __forceinline__ float sigf(float x)     { return 1.f / (1.f + __expf(-x)); }
__device__ __forceinline__ float tanhfast(float x) { return 2.f / (1.f + __expf(-2.f*x)) - 1.f; }

__device__ __forceinline__ void cpasync16(uint32_t dst, const void* src) {
    asm volatile("cp.async.cg.shared.global [%0], [%1], 16;" :: "r"(dst), "l"(src));
}
__device__ __forceinline__ void cpcommit() { asm volatile("cp.async.commit_group;"); }
__device__ __forceinline__ void cpwait1()  { asm volatile("cp.async.wait_group 1;"); }
__device__ __forceinline__ void cpwait0()  { asm volatile("cp.async.wait_group 0;"); }

__device__ __forceinline__ void ldmx4(uint32_t addr, uint32_t* r) {
    asm volatile("ldmatrix.sync.aligned.m8n8.x4.shared.b16 {%0,%1,%2,%3}, [%4];"
                 : "=r"(r[0]), "=r"(r[1]), "=r"(r[2]), "=r"(r[3]) : "r"(addr));
}

#define MMA_BF16(c, a, b0, b1) \
    asm volatile("mma.sync.aligned.m16n8k16.row.col.f32.bf16.bf16.f32 " \
                 "{%0,%1,%2,%3}, {%4,%5,%6,%7}, {%8,%9}, {%0,%1,%2,%3};" \
                 : "+f"((c)[0]), "+f"((c)[1]), "+f"((c)[2]), "+f"((c)[3]) \
                 : "r"((a)[0]), "r"((a)[1]), "r"((a)[2]), "r"((a)[3]), \
                   "r"(b0), "r"(b1))

__device__ __forceinline__ void bsplit4(__nv_bfloat16* hi, __nv_bfloat16* lo, int i,
                                        float x, float y, float z, float w)
{
    __nv_bfloat16 hx = __float2bfloat16(x), hy = __float2bfloat16(y);
    __nv_bfloat16 hz = __float2bfloat16(z), hw = __float2bfloat16(w);
    ((__nv_bfloat162*)hi)[2*i]   = __nv_bfloat162(hx, hy);
    ((__nv_bfloat162*)hi)[2*i+1] = __nv_bfloat162(hz, hw);
    ((__nv_bfloat162*)lo)[2*i]   = __nv_bfloat162(__float2bfloat16(x - __bfloat162float(hx)),
                                                  __float2bfloat16(y - __bfloat162float(hy)));
    ((__nv_bfloat162*)lo)[2*i+1] = __nv_bfloat162(__float2bfloat16(z - __bfloat162float(hz)),
                                                  __float2bfloat16(w - __bfloat162float(hw)));
}

// ================= mma.sync split-bf16 GEMM (unchanged from R13, passing) =================
#define KC      32
#define PITCHB  80u
#define TILE_B  (128u * PITCHB)
#define BUF_B   (4u * TILE_B)
#define TGS_SMEM (2 * BUF_B)

__global__ __launch_bounds__(256) void tgemm_kernel(
    const __nv_bfloat16* __restrict__ Ah, const __nv_bfloat16* __restrict__ Al,
    const __nv_bfloat16* __restrict__ Bh, const __nv_bfloat16* __restrict__ Bl,
    int ldB, int kofs,
    float* __restrict__ C, int ldC, int accum)
{
    extern __shared__ __align__(16) char smraw[];
    const uint32_t sb = (uint32_t)__cvta_generic_to_shared(smraw);

    const int tid  = threadIdx.x;
    const int wid  = tid >> 5;
    const int lane = tid & 31;
    const int bm   = blockIdx.y * 128;
    const int bn   = blockIdx.x * 128;
    const int wm   = wid & 3;
    const int wn   = wid >> 2;

    float acc[2][8][4];
#pragma unroll
    for (int i = 0; i < 2; i++)
#pragma unroll
        for (int j = 0; j < 8; j++)
#pragma unroll
            for (int k = 0; k < 4; k++) acc[i][j][k] = 0.f;

    auto stage = [&](int buf, int k0) {
        uint32_t base = sb + (uint32_t)buf * BUF_B;
#pragma unroll
        for (int r = 0; r < 8; r++) {
            int id   = tid + 256 * r;
            int tile = id >> 9;
            int row  = (id >> 2) & 127;
            int g    = id & 3;
            uint32_t daddr = base + (uint32_t)tile * TILE_B + (uint32_t)row * PITCHB + (uint32_t)g * 16u;
            const __nv_bfloat16* src;
            if      (tile == 0) src = Ah + (size_t)(bm + row) * 1024 + k0 + g * 8;
            else if (tile == 1) src = Al + (size_t)(bm + row) * 1024 + k0 + g * 8;
            else if (tile == 2) src = Bh + (size_t)(bn + row) * ldB + kofs + k0 + g * 8;
            else                src = Bl + (size_t)(bn + row) * ldB + kofs + k0 + g * 8;
            cpasync16(daddr, src);
        }
    };

    stage(0, 0); cpcommit();

    for (int ch = 0; ch < 1024 / KC; ch++) {
        if (ch + 1 < 1024 / KC) { stage((ch + 1) & 1, (ch + 1) * KC); cpcommit(); cpwait1(); }
        else                    { cpwait0(); }
        __syncthreads();

        uint32_t base = sb + (uint32_t)(ch & 1) * BUF_B;
#pragma unroll
        for (int ks = 0; ks < 2; ks++) {
            uint32_t ah[2][4], al[2][4], bh[4][4], bl[4][4];
#pragma unroll
            for (int tm = 0; tm < 2; tm++) {
                uint32_t row = (uint32_t)(wm * 32 + tm * 16 + (lane & 15));
                uint32_t addr = base + row * PITCHB + (uint32_t)(ks * 32) + (uint32_t)((lane >> 4) * 16);
                ldmx4(addr, ah[tm]);
                ldmx4(addr + TILE_B, al[tm]);
            }
#pragma unroll
            for (int tb = 0; tb < 4; tb++) {
                uint32_t rn = (uint32_t)(wn * 64 + tb * 16 + ((lane >> 4) << 3) + (lane & 7));
                uint32_t addr = base + 2u * TILE_B + rn * PITCHB + (uint32_t)(ks * 32) + (uint32_t)(((lane >> 3) & 1) * 16);
                ldmx4(addr, bh[tb]);
                ldmx4(addr + TILE_B, bl[tb]);
            }
#pragma unroll
            for (int tm = 0; tm < 2; tm++)
#pragma unroll
                for (int tn = 0; tn < 8; tn++) {
                    int tb = tn >> 1, s = (tn & 1) * 2;
                    MMA_BF16(acc[tm][tn], ah[tm], bh[tb][s], bh[tb][s + 1]);
                    MMA_BF16(acc[tm][tn], ah[tm], bl[tb][s], bl[tb][s + 1]);
                    MMA_BF16(acc[tm][tn], al[tm], bh[tb][s], bh[tb][s + 1]);
                }
        }
        __syncthreads();
    }

    const int r0 = bm + wm * 32 + (lane >> 2);
    const int cb = bn + wn * 64 + (lane & 3) * 2;
#pragma unroll
    for (int tm = 0; tm < 2; tm++)
#pragma unroll
        for (int tn = 0; tn < 8; tn++) {
            float* p0 = C + (size_t)(r0 + tm * 16) * ldC + cb + tn * 8;
            float* p1 = p0 + 8 * (size_t)ldC;
            if (accum) {
                float2 d0 = *(float2*)p0;
                d0.x += acc[tm][tn][0]; d0.y += acc[tm][tn][1];
                *(float2*)p0 = d0;
                float2 d1 = *(float2*)p1;
                d1.x += acc[tm][tn][2]; d1.y += acc[tm][tn][3];
                *(float2*)p1 = d1;
            } else {
                *(float2*)p0 = make_float2(acc[tm][tn][0], acc[tm][tn][1]);
                *(float2*)p1 = make_float2(acc[tm][tn][2], acc[tm][tn][3]);
            }
        }
}

// ================= persistent scan kernel =================
// 128 blocks x 128 threads, all resident (166.6 KB smem -> 1 block/SM).
// Block owns d-cols [blk*8, blk*8+8); Whh slice (24 rows x 1024) lives in smem
// for all 128 steps. Steps separated by a software grid barrier (monotonic).
#define SC_WPITCH 1032
#define SC_HPITCH 132
#define SC_WS_FLOATS (24 * SC_WPITCH)        // 24768
#define SC_HS_FLOATS (64 * SC_HPITCH)        // 8448
#define SCAN_SMEM_BYTES ((SC_WS_FLOATS + 2 * SC_HS_FLOATS) * 4)   // 166,656

__global__ __launch_bounds__(128) void scan_kernel(
    float* hA, float* hB,
    const float* __restrict__ GI, const float* __restrict__ GG,
    const float* __restrict__ Whh,
    const float* __restrict__ bih, const float* __restrict__ bhh)
{
    extern __shared__ float sm[];
    float* ws = sm;
    float* hs = sm + SC_WS_FLOATS;

    const int tid = threadIdx.x;
    const int w   = tid >> 5;
    const int l   = tid & 31;
    const int dl  = l & 1;
    const int bg  = l >> 1;
    const int dloc = w * 2 + dl;
    const int bd0 = blockIdx.x * 8;
    const int d   = bd0 + dloc;

    const uint32_t hs_sm = (uint32_t)__cvta_generic_to_shared(hs);

    // load weight slice once: 24 rows x 1024 (6144 float4)
    for (int i = tid; i < 6144; i += 128) {
        int row = i >> 8, g = i & 255;
        int gate = row >> 3, dd = row & 7;
        float4 v = *(const float4*)(Whh + (size_t)(gate * 1024 + bd0 + dd) * 1024 + g * 4);
        *(float4*)&ws[row * SC_WPITCH + g * 4] = v;
    }
    __syncthreads();

    const float bir = bih[d], biz = bih[1024 + d], bin = bih[2048 + d];
    const float bhr = bhh[d], bhz = bhh[1024 + d], bhn = bhh[2048 + d];

    for (int t = 0; t < T_; t++) {
        const float* h_in = (t & 1) ? hB : hA;
        float*       h_out = (t & 1) ? hA : hB;
        const float* gi_t = GI + (size_t)t * B_ * D3_;
        const float* gg_t = GG + (size_t)t * B_ * D_;

        // stage chunk 0
        {
#pragma unroll
            for (int r = 0; r < 16; r++) {
                int i = tid + 128 * r;
                int row = i >> 5, g = i & 31;
                cpasync16(hs_sm + (uint32_t)(row * SC_HPITCH + g * 4) * 4u,
                          h_in + (size_t)row * 1024 + g * 4);
            }
            cpcommit();
        }

        // prefetch epilogue operands (hide L2 latency behind compute)
        float hp4[4], gir4[4], giz4[4], gin4[4], G4[4];
#pragma unroll
        for (int i = 0; i < 4; i++) {
            int b = bg + 16 * i;
            hp4[i]  = h_in[b * 1024 + d];
            gir4[i] = gi_t[b * 3072 + d];
            giz4[i] = gi_t[b * 3072 + 1024 + d];
            gin4[i] = gi_t[b * 3072 + 2048 + d];
            G4[i]   = gg_t[b * 1024 + d];
        }

        ull accx[12], accy[12];
#pragma unroll
        for (int i = 0; i < 12; i++) { accx[i] = 0ull; accy[i] = 0ull; }

        for (int ch = 0; ch < 8; ch++) {
            if (ch < 7) {
                int nb = (ch + 1) & 1;
                int k0 = (ch + 1) * 128;
#pragma unroll
                for (int r = 0; r < 16; r++) {
                    int i = tid + 128 * r;
                    int row = i >> 5, g = i & 31;
                    cpasync16(hs_sm + (uint32_t)(nb * SC_HS_FLOATS + row * SC_HPITCH + g * 4) * 4u,
                              h_in + (size_t)row * 1024 + k0 + g * 4);
                }
                cpcommit(); cpwait1();
            } else {
                cpwait0();
            }
            __syncthreads();

            const float* hb = hs + (ch & 1) * SC_HS_FLOATS;
            const float* hp0 = hb + (bg +  0) * SC_HPITCH;
            const float* hp1 = hb + (bg + 16) * SC_HPITCH;
            const float* hp2 = hb + (bg + 32) * SC_HPITCH;
            const float* hp3 = hb + (bg + 48) * SC_HPITCH;
            const float* wp0 = ws + (0 * 8 + dloc) * SC_WPITCH + ch * 128;
            const float* wp1 = ws + (1 * 8 + dloc) * SC_WPITCH + ch * 128;
            const float* wp2 = ws + (2 * 8 + dloc) * SC_WPITCH + ch * 128;

#pragma unroll 8
            for (int kk = 0; kk < 128; kk += 4) {
                ulonglong2 wv0 = *(const ulonglong2*)(wp0 + kk);
                ulonglong2 wv1 = *(const ulonglong2*)(wp1 + kk);
                ulonglong2 wv2 = *(const ulonglong2*)(wp2 + kk);
                ulonglong2 h0 = *(const ulonglong2*)(hp0 + kk);
                ulonglong2 h1 = *(const ulonglong2*)(hp1 + kk);
                ulonglong2 h2 = *(const ulonglong2*)(hp2 + kk);
                ulonglong2 h3 = *(const ulonglong2*)(hp3 + kk);
                ffma2(accx[0],  h0.x, wv0.x); ffma2(accx[1],  h0.x, wv1.x); ffma2(accx[2],  h0.x, wv2.x);
                ffma2(accx[3],  h1.x, wv0.x); ffma2(accx[4],  h1.x, wv1.x); ffma2(accx[5],  h1.x, wv2.x);
                ffma2(accx[6],  h2.x, wv0.x); ffma2(accx[7],  h2.x, wv1.x); ffma2(accx[8],  h2.x, wv2.x);
                ffma2(accx[9],  h3.x, wv0.x); ffma2(accx[10], h3.x, wv1.x); ffma2(accx[11], h3.x, wv2.x);
                ffma2(accy[0],  h0.y, wv0.y); ffma2(accy[1],  h0.y, wv1.y); ffma2(accy[2],  h0.y, wv2.y);
                ffma2(accy[3],  h1.y, wv0.y); ffma2(accy[4],  h1.y, wv1.y); ffma2(accy[5],  h1.y, wv2.y);
                ffma2(accy[6],  h2.y, wv0.y); ffma2(accy[7],  h2.y, wv1.y); ffma2(accy[8],  h2.y, wv2.y);
                ffma2(accy[9],  h3.y, wv0.y); ffma2(accy[10], h3.y, wv1.y); ffma2(accy[11], h3.y, wv2.y);
            }
            __syncthreads();
        }

        // epilogue
#pragma unroll
        for (int i = 0; i < 4; i++) {
            int b = bg + 16 * i;
            float dr = sum2(accx[i*3+0]) + sum2(accy[i*3+0]);
            float dz = sum2(accx[i*3+1]) + sum2(accy[i*3+1]);
            float dn = sum2(accx[i*3+2]) + sum2(accy[i*3+2]);
            float r = sigf(gir4[i] + bir + dr + bhr);
            float z = sigf(giz4[i] + biz + dz + bhz);
            float n = tanhfast(gin4[i] + bin + r * (dn + bhn));
            float hatt = (1.f - z) * n + z * hp4[i];
            h_out[b * 1024 + d] = G4[i] * hatt + (1.f - G4[i]) * hp4[i];
        }

        // grid barrier (monotonic counter; all 128 CTAs resident)
        __syncthreads();
        __threadfence();
        if (tid == 0) {
            atomicAdd(&g_barrier, 1);
            volatile int* bp = &g_barrier;
            int target = 128 * (t + 1);
            while (*bp < target) __nanosleep(32);
        }
        __syncthreads();
        __threadfence();
    }
}

__global__ void reset_barrier_kernel() { g_barrier = 0; }

// ---------------- small M=64 split-K GEMM: C += A[64,K] @ W[N,K]^T ----------------
// grid (N/64, K/256); atomicAdd epilogue; C must be zeroed first.
__global__ __launch_bounds__(256) void sgemm64_kernel(
    const float* __restrict__ A, int ldA,
    const float* __restrict__ W, int ldW,
    float* __restrict__ C, int ldC)
{
    __shared__ float As[16][68];
    __shared__ float Ws[16][68];
    const int tid = threadIdx.x;
    const int bn = blockIdx.x * 64;
    const int k0 = blockIdx.y * 256;
    const int tx = tid & 15, ty = tid >> 4;
    const int m0 = ty * 4, n0 = tx * 4;
    const int lrow = tid >> 2, lk = (tid & 3) * 4;

    ull acc[2][4];
#pragma unroll
    for (int i = 0; i < 2; i++)
#pragma unroll
        for (int j = 0; j < 4; j++) acc[i][j] = 0ull;

    for (int kc = 0; kc < 256; kc += 16) {
        float4 av = *(const float4*)(A + (size_t)lrow * ldA + k0 + kc + lk);
        float4 wv = *(const float4*)(W + (size_t)(bn + lrow) * ldW + k0 + kc + lk);
        __syncthreads();
        As[lk+0][lrow] = av.x; As[lk+1][lrow] = av.y; As[lk+2][lrow] = av.z; As[lk+3][lrow] = av.w;
        Ws[lk+0][lrow] = wv.x; Ws[lk+1][lrow] = wv.y; Ws[lk+2][lrow] = wv.z; Ws[lk+3][lrow] = wv.w;
        __syncthreads();
#pragma unroll
        for (int kk = 0; kk < 16; kk++) {
            ull a01 = *(const ull*)&As[kk][m0];
            ull a23 = *(const ull*)&As[kk][m0 + 2];
            float4 w4 = *(const float4*)&Ws[kk][n0];
            ull w0 = pk(w4.x, w4.x), w1 = pk(w4.y, w4.y);
            ull w2 = pk(w4.z, w4.z), w3 = pk(w4.w, w4.w);
            ffma2(acc[0][0], a01, w0); ffma2(acc[0][1], a01, w1);
            ffma2(acc[0][2], a01, w2); ffma2(acc[0][3], a01, w3);
            ffma2(acc[1][0], a23, w0); ffma2(acc[1][1], a23, w1);
            ffma2(acc[1][2], a23, w2); ffma2(acc[1][3], a23, w3);
        }
    }
#pragma unroll
    for (int j = 0; j < 4; j++) {
        float2 v0 = upk(acc[0][j]);
        float2 v1 = upk(acc[1][j]);
        atomicAdd(&C[(size_t)(m0 + 0) * ldC + bn + n0 + j], v0.x);
        atomicAdd(&C[(size_t)(m0 + 1) * ldC + bn + n0 + j], v0.y);
        atomicAdd(&C[(size_t)(m0 + 2) * ldC + bn + n0 + j], v1.x);
        atomicAdd(&C[(size_t)(m0 + 3) * ldC + bn + n0 + j], v1.y);
    }
}

// ---------------- elementwise kernels ----------------
__global__ void split_kernel(const float* __restrict__ s, __nv_bfloat16* __restrict__ hi,
                             __nv_bfloat16* __restrict__ lo, int n4)
{
    int i = blockIdx.x * 256 + threadIdx.x;
    if (i >= n4) return;
    float4 v = ((const float4*)s)[i];
    bsplit4(hi, lo, i, v.x, v.y, v.z, v.w);
}

// features -> split bf16 directly: FA=c*x, FB=|c-x|, FC=c*y
__global__ void feat3b_kernel(const float* __restrict__ c, const float* __restrict__ x,
                              const float* __restrict__ y,
                              __nv_bfloat16* __restrict__ FAh, __nv_bfloat16* __restrict__ FAl,
                              __nv_bfloat16* __restrict__ FBh, __nv_bfloat16* __restrict__ FBl,
                              __nv_bfloat16* __restrict__ FCh, __nv_bfloat16* __restrict__ FCl)
{
    int i = blockIdx.x * 256 + threadIdx.x;
    int bc = ((i >> 8) & 63) * 256 + (i & 255);
    float4 cv = ((const float4*)c)[i];
    float4 xv = ((const float4*)x)[bc];
    float4 yv = ((const float4*)y)[bc];
    bsplit4(FAh, FAl, i, cv.x*xv.x, cv.y*xv.y, cv.z*xv.z, cv.w*xv.w);
    bsplit4(FBh, FBl, i, fabsf(cv.x-xv.x), fabsf(cv.y-xv.y), fabsf(cv.z-xv.z), fabsf(cv.w-xv.w));
    bsplit4(FCh, FCl, i, cv.x*yv.x, cv.y*yv.y, cv.z*yv.z, cv.w*yv.w);
}

__global__ void addrow_kernel(const float* __restrict__ S0, const float* __restrict__ rc,
                              float* __restrict__ S)
{
    int i = blockIdx.x * 256 + threadIdx.x;
    int bc = ((i >> 8) & 63) * 256 + (i & 255);
    float4 a = ((const float4*)S0)[i];
    float4 r = ((const float4*)rc)[bc];
    ((float4*)S)[i] = make_float4(a.x+r.x, a.y+r.y, a.z+r.z, a.w+r.w);
}

__global__ void tanhsplit_kernel(const float* __restrict__ S,
                                 __nv_bfloat16* __restrict__ hi, __nv_bfloat16* __restrict__ lo)
{
    int i = blockIdx.x * 256 + threadIdx.x;
    float4 v = ((const float4*)S)[i];
    bsplit4(hi, lo, i, tanhfast(v.x), tanhfast(v.y), tanhfast(v.z), tanhfast(v.w));
}

__global__ void sigbias_kernel(float* __restrict__ G, const float* __restrict__ bias)
{
    int i = blockIdx.x * 256 + threadIdx.x;
    float4 b = ((const float4*)bias)[i & 255];
    float4 v = ((float4*)G)[i];
    ((float4*)G)[i] = make_float4(sigf(v.x+b.x), sigf(v.y+b.y), sigf(v.z+b.z), sigf(v.w+b.w));
}

// rc = rc + rcq + bias_row
__global__ void rowbias2_kernel(float* __restrict__ rc, const float* __restrict__ rcq,
                                const float* __restrict__ bias)
{
    int i = blockIdx.x * 256 + threadIdx.x;
    float4 b = ((const float4*)bias)[i & 255];
    float4 v = ((float4*)rc)[i];
    float4 u = ((const float4*)rcq)[i];
    ((float4*)rc)[i] = make_float4(v.x+u.x+b.x, v.y+u.y+b.y, v.z+u.z+b.z, v.w+u.w+b.w);
}

__global__ void zero_kernel(float* __restrict__ p, int n4)
{
    int i = blockIdx.x * 256 + threadIdx.x;
    if (i < n4) ((float4*)p)[i] = make_float4(0.f, 0.f, 0.f, 0.f);
}

__global__ void gruew_kernel(const float* __restrict__ gi, const float* __restrict__ gh,
                             const float* __restrict__ h,  const float* __restrict__ bih,
                             const float* __restrict__ bhh, float* __restrict__ out)
{
    int i = blockIdx.x * 256 + threadIdx.x;
    int b = i >> 10, d = i & 1023;
    float gir = gi[b*3072 + d]        + bih[d];
    float giz = gi[b*3072 + 1024 + d] + bih[1024 + d];
    float gin = gi[b*3072 + 2048 + d] + bih[2048 + d];
    float ghr = gh[b*3072 + d]        + bhh[d];
    float ghz = gh[b*3072 + 1024 + d] + bhh[1024 + d];
    float ghn = gh[b*3072 + 2048 + d] + bhh[2048 + d];
    float r = sigf(gir + ghr);
    float z = sigf(giz + ghz);
    float n = tanhfast(gin + r * ghn);
    out[i] = (1.f - z) * n + z * h[i];
}

// ---------------- host orchestration ----------------
static void tgemm(const __nv_bfloat16* Ah, const __nv_bfloat16* Al,
                  const __nv_bfloat16* Bh, const __nv_bfloat16* Bl,
                  int ldB, int kofs, float* C, int ldC, int N, int accum)
{
    dim3 g(N / 128, TB_ / 128);
    tgemm_kernel<<<g, 256, TGS_SMEM>>>(Ah, Al, Bh, Bl, ldB, kofs, C, ldC, accum);
}

static void sgemm64(const float* A, int ldA, const float* W, int ldW,
                    float* C, int ldC, int N)
{
    dim3 g(N / 64, 4);
    sgemm64_kernel<<<g, 256>>>(A, ldA, W, ldW, C, ldC);
}

extern "C" void kernel_launch(void* const* d_in, const int* in_sizes, int n_in,
                              void* d_out, int out_size)
{
    const float* c    = (const float*)d_in[0];
    const float* q    = (const float*)d_in[1];
    const float* Wb   = (const float*)d_in[2];
    const float* W1   = (const float*)d_in[3];
    const float* W1b  = (const float*)d_in[4];
    const float* W2   = (const float*)d_in[5];
    const float* W2b  = (const float*)d_in[6];
    const float* mWih = (const float*)d_in[7];
    const float* mWhh = (const float*)d_in[8];
    const float* mbih = (const float*)d_in[9];
    const float* mbhh = (const float*)d_in[10];
    const float* aWih = (const float*)d_in[11];
    const float* aWhh = (const float*)d_in[12];
    const float* abih = (const float*)d_in[13];
    const float* abhh = (const float*)d_in[14];

    cudaFuncSetAttribute(tgemm_kernel, cudaFuncAttributeMaxDynamicSharedMemorySize, TGS_SMEM);
    cudaFuncSetAttribute(scan_kernel,  cudaFuncAttributeMaxDynamicSharedMemorySize, SCAN_SMEM_BYTES);

    float *pG, *pSinv, *pS, *pGI, *pWbq, *pWbm, *prc, *prcq;
    float *ph0, *ph1, *pm, *pm2, *pgi, *pgh;
    __nv_bfloat16 *bAh, *bAl, *FAh, *FAl, *FBh, *FBl, *FCh, *FCl;
    __nv_bfloat16 *bW1h, *bW1l, *bW2h, *bW2l, *bWihh, *bWihl;
    cudaGetSymbolAddress((void**)&pG,    g_FAg);
    cudaGetSymbolAddress((void**)&pSinv, g_Sinv);
    cudaGetSymbolAddress((void**)&pS,    g_S);
    cudaGetSymbolAddress((void**)&pGI,   g_GI);
    cudaGetSymbolAddress((void**)&pWbq,  g_Wbq);
    cudaGetSymbolAddress((void**)&pWbm,  g_Wbm);
    cudaGetSymbolAddress((void**)&prc,   g_rc);
    cudaGetSymbolAddress((void**)&prcq,  g_rcq);
    cudaGetSymbolAddress((void**)&ph0,   g_h0);
    cudaGetSymbolAddress((void**)&ph1,   g_h1);
    cudaGetSymbolAddress((void**)&pm,    g_m);
    cudaGetSymbolAddress((void**)&pm2,   g_m2);
    cudaGetSymbolAddress((void**)&pgi,   g_gi);
    cudaGetSymbolAddress((void**)&pgh,   g_gh);
    cudaGetSymbolAddress((void**)&bAh,   g_bAh);
    cudaGetSymbolAddress((void**)&bAl,   g_bAl);
    cudaGetSymbolAddress((void**)&FAh,   g_FAh);
    cudaGetSymbolAddress((void**)&FAl,   g_FAl);
    cudaGetSymbolAddress((void**)&FBh,   g_FBh);
    cudaGetSymbolAddress((void**)&FBl,   g_FBl);
    cudaGetSymbolAddress((void**)&FCh,   g_FCh);
    cudaGetSymbolAddress((void**)&FCl,   g_FCl);
    cudaGetSymbolAddress((void**)&bW1h,  g_W1h);
    cudaGetSymbolAddress((void**)&bW1l,  g_W1l);
    cudaGetSymbolAddress((void**)&bW2h,  g_W2h);
    cudaGetSymbolAddress((void**)&bW2l,  g_W2l);
    cudaGetSymbolAddress((void**)&bWihh, g_Wihh);
    cudaGetSymbolAddress((void**)&bWihl, g_Wihl);

    const int GRID_TBD4 = (TB_ * D_ / 4) / 256;   // 8192
    const int BD4  = B_ * D_ / 4;                 // 16384
    const int BD34 = B_ * D3_ / 4;                // 49152
    const int GRID_BD4  = BD4 / 256;              // 64
    const int GRID_BD34 = BD34 / 256;             // 192
    const int GRID_BD   = (B_ * D_) / 256;        // 256

    cudaMemcpyAsync(pm, q, (size_t)B_ * D_ * sizeof(float), cudaMemcpyDeviceToDevice);

    // weight splits
    split_kernel<<<(D_*D9_/4)/256, 256>>>(W1, bW1h, bW1l, D_*D9_/4);
    split_kernel<<<(D_*D_/4)/256, 256>>>(W2, bW2h, bW2l, D_*D_/4);
    split_kernel<<<(D3_*D_/4)/256, 256>>>(aWih, bWihh, bWihl, D3_*D_/4);

    // episode-invariant precompute
    zero_kernel<<<GRID_BD4, 256>>>(pWbq, BD4);
    sgemm64(q, D_, Wb, D_, pWbq, D_, D_);                        // Wbq = q @ Wb^T
    zero_kernel<<<GRID_BD4, 256>>>(prcq, BD4);
    sgemm64(q, D_, W1 + 2*D_, D9_, prcq, D_, D_);                // rcq = q @ V2^T (hoisted)

    feat3b_kernel<<<GRID_TBD4, 256>>>(c, q, pWbq, FAh, FAl, FBh, FBl, FCh, FCl);
    split_kernel<<<GRID_TBD4, 256>>>(c, bAh, bAl, TB_*D_/4);

    tgemm(bAh, bAl, bW1h, bW1l, D9_, 0*D_, pSinv, D_, D_, 0);    // c @ V0^T
    tgemm(bAh, bAl, bWihh, bWihl, D_, 0, pGI, D3_, D3_, 0);      // gi_att all t
    tgemm(FAh, FAl, bW1h, bW1l, D9_, 3*D_, pSinv, D_, D_, 1);    // + c*q   @ V3^T
    tgemm(FBh, FBl, bW1h, bW1l, D9_, 5*D_, pSinv, D_, D_, 1);    // + |c-q| @ V5^T
    tgemm(FCh, FCl, bW1h, bW1l, D9_, 7*D_, pSinv, D_, D_, 1);    // + c*Wbq @ V7^T

    float* mc = pm;
    float* mn = pm2;
    for (int ep = 0; ep < 2; ep++) {
        zero_kernel<<<GRID_BD4, 256>>>(pWbm, BD4);
        sgemm64(mc, D_, Wb, D_, pWbm, D_, D_);                   // Wbm = m @ Wb^T
        zero_kernel<<<GRID_BD4, 256>>>(prc, BD4);
        sgemm64(mc, D_, W1 + 1*D_, D9_, prc, D_, D_);            // m @ V1^T
        rowbias2_kernel<<<GRID_BD4, 256>>>(prc, prcq, W1b);      // + q@V2^T + W1_b

        feat3b_kernel<<<GRID_TBD4, 256>>>(c, mc, pWbm, FAh, FAl, FBh, FBl, FCh, FCl);
        addrow_kernel<<<GRID_TBD4, 256>>>(pSinv, prc, pS);       // S = Sinv + rowconst

        tgemm(FAh, FAl, bW1h, bW1l, D9_, 4*D_, pS, D_, D_, 1);   // + c*m   @ V4^T
        tgemm(FBh, FBl, bW1h, bW1l, D9_, 6*D_, pS, D_, D_, 1);   // + |c-m| @ V6^T
        tgemm(FCh, FCl, bW1h, bW1l, D9_, 8*D_, pS, D_, D_, 1);   // + c*Wbm @ V8^T

        tanhsplit_kernel<<<GRID_TBD4, 256>>>(pS, bAh, bAl);      // g1 = tanh(S), split
        tgemm(bAh, bAl, bW2h, bW2l, D_, 0, pG, D_, D_, 0);       // Gpre
        sigbias_kernel<<<GRID_TBD4, 256>>>(pG, W2b);             // G = sigmoid(Gpre + b2)

        zero_kernel<<<GRID_BD4, 256>>>(ph0, BD4);                // h = 0
        reset_barrier_kernel<<<1, 1>>>();
        scan_kernel<<<128, 128, SCAN_SMEM_BYTES>>>(ph0, ph1, pGI, pG, aWhh, abih, abhh);
        // e ends in ph0 (128 steps: last write hits ph0)

        zero_kernel<<<GRID_BD34, 256>>>(pgi, BD34);
        sgemm64(ph0, D_, mWih, D_, pgi, D3_, D3_);               // e @ mem_Wih^T
        zero_kernel<<<GRID_BD34, 256>>>(pgh, BD34);
        sgemm64(mc, D_, mWhh, D_, pgh, D3_, D3_);                // m @ mem_Whh^T
        gruew_kernel<<<GRID_BD, 256>>>(pgi, pgh, mc, mbih, mbhh, mn);
        float* tmp = mc; mc = mn; mn = tmp;
    }

    cudaMemcpyAsync(d_out, mc, (size_t)B_ * D_ * sizeof(float), cudaMemcpyDeviceToDevice);
}